// round 5
// baseline (speedup 1.0000x reference)
#include <cuda_runtime.h>
#include <cuda_bf16.h>
#include <math.h>
#include <stdint.h>

typedef unsigned short u16;
typedef uint32_t u32;
typedef uint64_t u64;

#define C_    768
#define P_    1024
#define KBIG  20736          // logical K: 9 taps x 3 slots x 768
#define LDA1  13824          // phys A1 row: 9 taps x 2 seg x 768
#define KFIN  4608           // logical: [blk 3x768 | x 3x768]
#define LDA2  3072           // phys A2 row: [blk hi|lo | x hi|lo]
#define LDBF  4608
#define MBIG  20480
#define TM    128
#define TN    256
#define THREADS 512
#define STG_BYTES 49152      // A 16KB + B 32KB
#define DYN_SMEM (3 * STG_BYTES)

// ---------------- static scratch ---------------------------------------------
__device__ u16  g_A1[(size_t)MBIG * LDA1];         // sampled A, 2-slot
__device__ u16  g_A2[(size_t)5 * 4096 * LDA2];     // [blk | x] 2-slot
__device__ u16  g_B1[(size_t)C_ * KBIG];           // conv weights 3-slot
__device__ u16  g_Bfin[(size_t)5 * 512 * LDBF];    // 1x1 weights 3-slot, padded
__device__ float g_om[(size_t)MBIG * C_];
__device__ float g_off[20 * 18 * P_];
__device__ float g_mask[20 * 9 * P_];
__device__ float g_scale[C_], g_shift[C_];

struct X5  { const float* p[5]; };
struct W10 { const float* a[5]; const float* b[5]; };
struct Fin { int chN[5]; int coff[5]; int nk[5]; };

// ---------------- helpers ----------------------------------------------------
__device__ __forceinline__ void split2(float v, u16& h, u16& l) {
    __nv_bfloat16 hb = __float2bfloat16(v);
    h = __bfloat16_as_ushort(hb);
    l = __bfloat16_as_ushort(__float2bfloat16(v - __bfloat162float(hb)));
}
__device__ __forceinline__ u32 pack2(float a, float b, int wantLo) {
    u16 ha, la, hb, lb; split2(a, ha, la); split2(b, hb, lb);
    return wantLo ? ((u32)la | ((u32)lb << 16)) : ((u32)ha | ((u32)hb << 16));
}
__device__ __forceinline__ u32 s2u(const void* p) {
    return (u32)__cvta_generic_to_shared(p);
}
__device__ __forceinline__ void cpa16(u32 s, const void* g) {
    asm volatile("cp.async.cg.shared.global [%0], [%1], 16;"
                 :: "r"(s), "l"((u64)__cvta_generic_to_global((void*)g)));
}
#define CP_COMMIT() asm volatile("cp.async.commit_group;")
#define CP_WAIT1()  asm volatile("cp.async.wait_group 1;")
#define SWZ(o) ((o) ^ (((o) >> 3) & 0x70))
#define STS16(addr, a, b, c, d) \
    asm volatile("st.shared.v4.b32 [%0], {%1,%2,%3,%4};" \
                 :: "r"(addr), "r"(a), "r"(b), "r"(c), "r"(d))
#define LDSM4(r0, r1, r2, r3, addr) \
    asm volatile("ldmatrix.sync.aligned.m8n8.x4.shared.b16 {%0,%1,%2,%3}, [%4];" \
        : "=r"(r0), "=r"(r1), "=r"(r2), "=r"(r3) : "r"(addr))
#define MMA16816(d, a0, a1, a2, a3, b0, b1) \
    asm volatile("mma.sync.aligned.m16n8k16.row.col.f32.bf16.bf16.f32 " \
        "{%0,%1,%2,%3}, {%4,%5,%6,%7}, {%8,%9}, {%0,%1,%2,%3};" \
        : "+f"((d)[0]), "+f"((d)[1]), "+f"((d)[2]), "+f"((d)[3]) \
        : "r"(a0), "r"(a1), "r"(a2), "r"(a3), "r"(b0), "r"(b1))

// ---------------- weight / BN prep -------------------------------------------
__global__ void bconv_k(const float* __restrict__ w) {
    size_t i = (size_t)blockIdx.x * 256 + threadIdx.x;
    if (i >= (size_t)C_ * C_ * 9) return;
    int k = (int)(i % 9);
    size_t t = i / 9;
    int c = (int)(t % C_), o = (int)(t / C_);
    u16 h, l; split2(w[i], h, l);
    u16* dst = g_B1 + (size_t)o * KBIG + (size_t)k * 2304 + c;
    dst[0] = h; dst[768] = h; dst[1536] = l;       // slots [Bh, Bh, Bl]
}

__global__ void bfin_k(W10 ws) {
    size_t i = (size_t)blockIdx.x * 256 + threadIdx.x;
    if (i >= (size_t)5 * 512 * 1536) return;
    int cc = (int)(i % 1536);
    size_t t = i / 1536;
    int j = (int)(t % 512), b = (int)(t / 512);
    int half = cc / 768, c = cc % 768;
    const int CH[5] = {30, 100, 150, 220, 268};
    float v = 0.f;
    if (j < CH[b]) {
        if (half == 0) v = ws.a[b][j * C_ + c];
        else if (b >= 2) v = ws.b[b][j * C_ + c];
    }
    u16 h, l; split2(v, h, l);
    u16* dst = g_Bfin + ((size_t)b * 512 + j) * LDBF + half * 2304 + c;
    dst[0] = h; dst[768] = h; dst[1536] = l;
}

__global__ void bnprep_k(const float* g, const float* bt, const float* mu,
                         const float* var, const float* cb) {
    int c = blockIdx.x * 256 + threadIdx.x;
    if (c >= C_) return;
    float inv = g[c] / sqrtf(var[c] + 1e-5f);
    g_scale[c] = inv;
    g_shift[c] = cb[c] * inv + bt[c] - mu[c] * inv;
}

// ---------------- 2-seg split writer helper ----------------------------------
__device__ __forceinline__ void store_split4_2seg(u32* base32, int tid, float4 v) {
    u16 h0, l0, h1, l1, h2, l2, h3, l3;
    split2(v.x, h0, l0); split2(v.y, h1, l1);
    split2(v.z, h2, l2); split2(v.w, h3, l3);
    base32[2 * tid]       = (u32)h0 | ((u32)h1 << 16);
    base32[2 * tid + 1]   = (u32)h2 | ((u32)h3 << 16);
    base32[384 + 2 * tid] = (u32)l0 | ((u32)l1 << 16);
    base32[385 + 2 * tid] = (u32)l2 | ((u32)l3 << 16);
}

__global__ void xsplit_k(X5 xs) {
    int row = blockIdx.x, b = blockIdx.y + 2;
    float4 v = ((const float4*)(xs.p[b] + (size_t)row * C_))[threadIdx.x];
    u32* base32 = (u32*)(g_A2 + ((size_t)b * 4096 + row) * LDA2 + 1536);
    store_split4_2seg(base32, threadIdx.x, v);
}

// ---------------- offset / mask heads ----------------------------------------
__global__ void offsets_k(const float* __restrict__ ow, const float* __restrict__ mw) {
    int lane = threadIdx.x & 31;
    int row = blockIdx.x * 8 + (threadIdx.x >> 5);
    const float* omr = g_om + (size_t)row * C_;
    float v[24];
#pragma unroll
    for (int i = 0; i < 24; i++) v[i] = omr[lane + 32 * i];
    float res[27];
#pragma unroll
    for (int o = 0; o < 27; o++) {
        const float* wr = (o < 18) ? (ow + o * C_) : (mw + (o - 18) * C_);
        float s = 0.f;
#pragma unroll
        for (int i = 0; i < 24; i++) s += v[i] * wr[lane + 32 * i];
#pragma unroll
        for (int d = 16; d; d >>= 1) s += __shfl_xor_sync(0xffffffffu, s, d);
        res[o] = s;
    }
    if (lane == 0) {
        int z = row >> 10, p = row & 1023;
#pragma unroll
        for (int o = 0; o < 18; o++) g_off[z * 18 * P_ + o * P_ + p] = res[o];
        float mx = res[18];
#pragma unroll
        for (int k = 1; k < 9; k++) mx = fmaxf(mx, res[18 + k]);
        float e[9], sum = 0.f;
#pragma unroll
        for (int k = 0; k < 9; k++) { e[k] = expf(res[18 + k] - mx); sum += e[k]; }
        float r = 1.f / sum;
#pragma unroll
        for (int k = 0; k < 9; k++) g_mask[z * 9 * P_ + p * 9 + k] = e[k] * r;
    }
}

// ---------------- deformable sampling, 2-seg out -----------------------------
__global__ void sample_split_k(X5 xs) {
    int p = blockIdx.x, k = blockIdx.y, z = blockIdx.z;
    int b = z >> 2;
    float dy = g_off[z * 18 * P_ + (2 * k) * P_ + p];
    float dx = g_off[z * 18 * P_ + (2 * k + 1) * P_ + p];
    float m = g_mask[z * 9 * P_ + k * P_ + p];            // raw-reshape quirk
    int h = p >> 5, w = p & 31;
    float py = (float)(h - 1 + k / 3) + dy;
    float px = (float)(w - 1 + k % 3) + dx;
    float y0f = floorf(py), x0f = floorf(px);
    float wy = py - y0f, wx = px - x0f;
    int y0 = (int)y0f, x0 = (int)x0f;
    float w00 = (1.f - wy) * (1.f - wx), w01 = (1.f - wy) * wx;
    float w10 = wy * (1.f - wx),         w11 = wy * wx;
    bool vy0 = (y0 >= 0) && (y0 < 32),  vy1 = (y0 >= -1) && (y0 < 31);
    bool vx0 = (x0 >= 0) && (x0 < 32),  vx1 = (x0 >= -1) && (x0 < 31);
    const float4* xb = (const float4*)(xs.p[b] + (size_t)(z & 3) * P_ * C_);
    int t = threadIdx.x;
    float4 a = make_float4(0.f, 0.f, 0.f, 0.f);
    if (vy0 && vx0) { float4 s = xb[(size_t)(y0 * 32 + x0) * 192 + t];
        a.x += w00 * s.x; a.y += w00 * s.y; a.z += w00 * s.z; a.w += w00 * s.w; }
    if (vy0 && vx1) { float4 s = xb[(size_t)(y0 * 32 + x0 + 1) * 192 + t];
        a.x += w01 * s.x; a.y += w01 * s.y; a.z += w01 * s.z; a.w += w01 * s.w; }
    if (vy1 && vx0) { float4 s = xb[(size_t)((y0 + 1) * 32 + x0) * 192 + t];
        a.x += w10 * s.x; a.y += w10 * s.y; a.z += w10 * s.z; a.w += w10 * s.w; }
    if (vy1 && vx1) { float4 s = xb[(size_t)((y0 + 1) * 32 + x0 + 1) * 192 + t];
        a.x += w11 * s.x; a.y += w11 * s.y; a.z += w11 * s.z; a.w += w11 * s.w; }
    a.x *= m; a.y *= m; a.z *= m; a.w *= m;
    size_t row = (size_t)z * P_ + p;
    u32* base32 = (u32*)(g_A1 + row * LDA1 + (size_t)k * 1536);
    store_split4_2seg(base32, t, a);
}

// ---------------- mma.sync bf16 GEMM -----------------------------------------
// AK=1: A fused im2col from x.  AK=3: A from 2-seg gmem with slot remap.
// MODE0: g_om = D + aux[col]; MODE1: split(relu(D*s+b)) -> g_A2 blk half;
// MODE2: out = D + x5 residual, z-batched final GEMMs.
template<int AK, int MODE>
__global__ void __launch_bounds__(THREADS, 1) gemm_mma(
    const u16* __restrict__ Ag, const u16* __restrict__ Bg,
    long lda, long ldb, int NKin, X5 xs,
    const float* __restrict__ aux, float* __restrict__ outp, Fin fin)
{
    extern __shared__ char sm[];
    u32 sbase = s2u(sm);
    const int tid = threadIdx.x;
    const int wid = tid >> 5, lane = tid & 31;
    const int wm = wid >> 2, wn = wid & 3;
    const int m0 = blockIdx.y * TM, n0 = blockIdx.x * TN;

    int NK = NKin, chN = 0, coff = 0;
    const u16* Abase = Ag;
    const u16* Bb0 = Bg;
    if (MODE == 2) {
        int b = blockIdx.z;
        chN = fin.chN[b]; coff = fin.coff[b]; NK = fin.nk[b];
        Abase = Ag + (size_t)b * 4096 * lda;
        Bb0 = Bg + (size_t)b * 512 * ldb;
        if (n0 >= chN) return;
    }
    const char* Bbase = (const char*)(Bb0 + (size_t)n0 * ldb);
    const long ldbb = ldb * 2;
    const int arow = tid >> 2, aq = tid & 3;

    auto loadStage = [&](int s, int kc) {
        u32 sb = sbase + s * STG_BYTES;
        u32 bb = sb + 16384;
        const char* Bgp = Bbase + (size_t)kc * 128;
#pragma unroll
        for (int it = 0; it < 4; it++) {
            int i = it * THREADS + tid;
            int row = i >> 3, c16 = i & 7;
            u32 off = (u32)(row * 128 + c16 * 16);
            cpa16(bb + SWZ(off), Bgp + (size_t)row * ldbb + c16 * 16);
        }
        CP_COMMIT();
        int tap = kc / 36, rem = kc % 36, slot = rem / 12, c0 = (rem % 12) << 6;
        u32 off = (u32)(arow * 128 + aq * 32);
        u32 d0 = sb + SWZ(off), d1 = sb + SWZ(off + 16);
        if (AK == 1) {
            int gr = m0 + arow;
            int bq = gr >> 12, n = (gr >> 10) & 3, p = gr & 1023;
            int hh = (p >> 5) + tap / 3 - 1, ww = (p & 31) + tap % 3 - 1;
            float4 f0, f1, f2, f3;
            if (hh >= 0 && hh < 32 && ww >= 0 && ww < 32) {
                const float4* src = (const float4*)(xs.p[bq] +
                    (size_t)((n << 10) + (hh << 5) + ww) * C_ + c0) + (aq << 2);
                f0 = src[0]; f1 = src[1]; f2 = src[2]; f3 = src[3];
            } else {
                f0 = f1 = f2 = f3 = make_float4(0.f, 0.f, 0.f, 0.f);
            }
            int wl = (slot == 1);
            STS16(d0, pack2(f0.x, f0.y, wl), pack2(f0.z, f0.w, wl),
                      pack2(f1.x, f1.y, wl), pack2(f1.z, f1.w, wl));
            STS16(d1, pack2(f2.x, f2.y, wl), pack2(f2.z, f2.w, wl),
                      pack2(f3.x, f3.y, wl), pack2(f3.z, f3.w, wl));
        } else {
            const uint4* src = (const uint4*)(Abase + (size_t)(m0 + arow) * lda +
                tap * 1536 + (slot == 1 ? 768 : 0) + c0) + aq * 2;
            uint4 v0 = src[0], v1 = src[1];
            STS16(d0, v0.x, v0.y, v0.z, v0.w);
            STS16(d1, v1.x, v1.y, v1.z, v1.w);
        }
    };

    float acc[2][8][4];
#pragma unroll
    for (int i = 0; i < 2; i++)
#pragma unroll
        for (int j = 0; j < 8; j++)
#pragma unroll
            for (int q = 0; q < 4; q++) acc[i][j][q] = 0.f;

    loadStage(0, 0);
    loadStage(1, 1);

    for (int kc = 0; kc < NK; kc++) {
        CP_WAIT1();
        __syncthreads();
        u32 ab = sbase + (kc % 3) * STG_BYTES;
        u32 bb = ab + 16384;
#pragma unroll
        for (int ks = 0; ks < 4; ks++) {
            u32 afr[2][4];
#pragma unroll
            for (int ms = 0; ms < 2; ms++) {
                int row = wm * 32 + ms * 16 + (lane & 15);
                u32 off = (u32)(row * 128 + ks * 32 + (lane >> 4) * 16);
                LDSM4(afr[ms][0], afr[ms][1], afr[ms][2], afr[ms][3], ab + SWZ(off));
            }
#pragma unroll
            for (int np = 0; np < 4; np++) {
                int g = lane >> 3;
                int row = wn * 64 + np * 16 + ((g >> 1) & 1) * 8 + (lane & 7);
                u32 off = (u32)(row * 128 + ks * 32 + (g & 1) * 16);
                u32 bfr[4];
                LDSM4(bfr[0], bfr[1], bfr[2], bfr[3], bb + SWZ(off));
#pragma unroll
                for (int ms = 0; ms < 2; ms++) {
                    MMA16816(acc[ms][2 * np], afr[ms][0], afr[ms][1], afr[ms][2],
                             afr[ms][3], bfr[0], bfr[1]);
                    MMA16816(acc[ms][2 * np + 1], afr[ms][0], afr[ms][1], afr[ms][2],
                             afr[ms][3], bfr[2], bfr[3]);
                }
            }
        }
        __syncthreads();
        int kl = kc + 2;
        if (kl < NK) loadStage(kl % 3, kl);
        else CP_COMMIT();
    }

    // epilogue
    int quad = lane >> 2, qt = lane & 3;
#pragma unroll
    for (int ms = 0; ms < 2; ms++) {
#pragma unroll
        for (int ns = 0; ns < 8; ns++) {
            int colb = n0 + wn * 64 + ns * 8 + 2 * qt;
#pragma unroll
            for (int hh = 0; hh < 2; hh++) {
                int row = m0 + wm * 32 + ms * 16 + quad + hh * 8;
                float v0 = acc[ms][ns][2 * hh], v1 = acc[ms][ns][2 * hh + 1];
                if (MODE == 0) {
                    g_om[(size_t)row * C_ + colb]     = v0 + aux[colb];
                    g_om[(size_t)row * C_ + colb + 1] = v1 + aux[colb + 1];
                } else if (MODE == 1) {
                    float t0 = fmaxf(v0 * g_scale[colb] + g_shift[colb], 0.f);
                    float t1 = fmaxf(v1 * g_scale[colb + 1] + g_shift[colb + 1], 0.f);
                    u16 h0, l0, h1, l1;
                    split2(t0, h0, l0); split2(t1, h1, l1);
                    u32* p32 = (u32*)(g_A2 + (size_t)row * LDA2);
                    int ci = colb >> 1;
                    p32[ci]       = (u32)h0 | ((u32)h1 << 16);
                    p32[384 + ci] = (u32)l0 | ((u32)l1 << 16);
                } else {
                    if (colb < chN)
                        outp[(size_t)row * C_ + coff + colb] =
                            v0 + aux[(size_t)row * C_ + coff + colb];
                    if (colb + 1 < chN)
                        outp[(size_t)row * C_ + coff + colb + 1] =
                            v1 + aux[(size_t)row * C_ + coff + colb + 1];
                }
            }
        }
    }
}

// ---------------- launch -----------------------------------------------------
extern "C" void kernel_launch(void* const* d_in, const int* in_sizes, int n_in,
                              void* d_out, int out_size) {
    static u16 *pA1 = 0, *pA2 = 0, *pB1 = 0, *pBf = 0;
    if (!pA1) {
        cudaGetSymbolAddress((void**)&pA1, g_A1);
        cudaGetSymbolAddress((void**)&pA2, g_A2);
        cudaGetSymbolAddress((void**)&pB1, g_B1);
        cudaGetSymbolAddress((void**)&pBf, g_Bfin);
        cudaFuncSetAttribute(gemm_mma<1, 0>,
                             cudaFuncAttributeMaxDynamicSharedMemorySize, DYN_SMEM);
        cudaFuncSetAttribute(gemm_mma<3, 1>,
                             cudaFuncAttributeMaxDynamicSharedMemorySize, DYN_SMEM);
        cudaFuncSetAttribute(gemm_mma<3, 2>,
                             cudaFuncAttributeMaxDynamicSharedMemorySize, DYN_SMEM);
    }
    X5 xs;
    for (int i = 0; i < 5; i++) xs.p[i] = (const float*)d_in[i];
    const float* conv_w = (const float*)d_in[5];
    const float* conv_b = (const float*)d_in[6];
    const float* offw   = (const float*)d_in[7];
    const float* maskw  = (const float*)d_in[8];
    W10 ws;
    const int waIdx[5] = {0, 1, 2, 4, 6};
    for (int b = 0; b < 5; b++) {
        ws.a[b] = (const float*)d_in[13 + waIdx[b]];
        ws.b[b] = (b >= 2) ? (const float*)d_in[13 + waIdx[b] + 1] : ws.a[b];
    }
    float* out = (float*)d_out;
    Fin fin;
    const int CH[5]   = {30, 100, 150, 220, 268};
    const int COFF[5] = {0, 30, 130, 280, 500};
    for (int b = 0; b < 5; b++) {
        fin.chN[b] = CH[b]; fin.coff[b] = COFF[b]; fin.nk[b] = (b < 2) ? 36 : 72;
    }

    bconv_k<<<(int)(((size_t)C_ * C_ * 9 + 255) / 256), 256>>>(conv_w);
    bfin_k<<<(int)(((size_t)5 * 512 * 1536 + 255) / 256), 256>>>(ws);
    bnprep_k<<<3, 256>>>((const float*)d_in[9], (const float*)d_in[10],
                         (const float*)d_in[11], (const float*)d_in[12], conv_b);
    xsplit_k<<<dim3(4096, 3), 192>>>(xs);

    gemm_mma<1, 0><<<dim3(3, 160), THREADS, DYN_SMEM>>>(
        nullptr, pB1, 0, KBIG, 324, xs, conv_b, nullptr, fin);
    offsets_k<<<2560, 256>>>(offw, maskw);
    sample_split_k<<<dim3(P_, 9, 20), 192>>>(xs);
    gemm_mma<3, 1><<<dim3(3, 160), THREADS, DYN_SMEM>>>(
        pA1, pB1, LDA1, KBIG, 324, xs, nullptr, nullptr, fin);
    gemm_mma<3, 2><<<dim3(2, 32, 5), THREADS, DYN_SMEM>>>(
        pA2, pBf, LDA2, LDBF, 0, xs, xs.p[4], out, fin);
}

// round 7
// speedup vs baseline: 1.4730x; 1.4730x over previous
#include <cuda_runtime.h>
#include <cuda_bf16.h>
#include <math.h>
#include <stdint.h>

typedef unsigned short u16;
typedef uint32_t u32;
typedef uint64_t u64;

#define C_    768
#define P_    1024
#define KBIG  20736          // logical K: 9 taps x 3 slots x 768
#define LDA1  13824          // sampled A phys row: 9 taps x [hi|lo] x 768
#define LDX   1536           // g_X2 / g_blk phys row: [hi 768 | lo 768]
#define LDBF  4608
#define MBIG  20480
#define TM    128
#define TN    256
#define THREADS 512
#define STG_BYTES 49152      // A 16KB + B 32KB
#define DYN_SMEM (3 * STG_BYTES)

// ---------------- static device scratch --------------------------------------
__device__ u16  g_X2[(size_t)MBIG * LDX];          // split inputs (all 5 blocks)
__device__ u16  g_blk[(size_t)MBIG * LDX];         // split block outputs
__device__ u16  g_A1[(size_t)MBIG * LDA1];         // split sampled A
__device__ u16  g_B1[(size_t)C_ * KBIG];           // conv weights 3-slot
__device__ u16  g_Bfin[(size_t)5 * 512 * LDBF];    // 1x1 weights 3-slot padded
__device__ float g_om[(size_t)MBIG * C_];
__device__ float g_off[20 * 18 * P_];
__device__ float g_mask[20 * 9 * P_];
__device__ float g_scale[C_], g_shift[C_];

struct X5  { const float* p[5]; };
struct W10 { const float* a[5]; const float* b[5]; };
struct Fin { int chN[5]; int coff[5]; int nk[5]; };

// ---------------- helpers ----------------------------------------------------
__device__ __forceinline__ void split2(float v, u16& h, u16& l) {
    __nv_bfloat16 hb = __float2bfloat16(v);
    h = __bfloat16_as_ushort(hb);
    l = __bfloat16_as_ushort(__float2bfloat16(v - __bfloat162float(hb)));
}
__device__ __forceinline__ u32 s2u(const void* p) {
    return (u32)__cvta_generic_to_shared(p);
}
__device__ __forceinline__ void cpa16(u32 s, const void* g) {
    asm volatile("cp.async.cg.shared.global [%0], [%1], 16;"
                 :: "r"(s), "l"((u64)__cvta_generic_to_global((void*)g)));
}
__device__ __forceinline__ void cpa16z(u32 s, const void* g, u32 sz) {
    asm volatile("cp.async.cg.shared.global [%0], [%1], 16, %2;"
                 :: "r"(s), "l"((u64)__cvta_generic_to_global((void*)g)), "r"(sz));
}
#define CP_COMMIT() asm volatile("cp.async.commit_group;")
#define CP_WAIT1()  asm volatile("cp.async.wait_group 1;")
#define SWZ(o) ((o) ^ (((o) >> 3) & 0x70))
#define LDSM4(r0, r1, r2, r3, addr) \
    asm volatile("ldmatrix.sync.aligned.m8n8.x4.shared.b16 {%0,%1,%2,%3}, [%4];" \
        : "=r"(r0), "=r"(r1), "=r"(r2), "=r"(r3) : "r"(addr))
#define MMA16816(d, a0, a1, a2, a3, b0, b1) \
    asm volatile("mma.sync.aligned.m16n8k16.row.col.f32.bf16.bf16.f32 " \
        "{%0,%1,%2,%3}, {%4,%5,%6,%7}, {%8,%9}, {%0,%1,%2,%3};" \
        : "+f"((d)[0]), "+f"((d)[1]), "+f"((d)[2]), "+f"((d)[3]) \
        : "r"(a0), "r"(a1), "r"(a2), "r"(a3), "r"(b0), "r"(b1))

// ---------------- weight / BN prep -------------------------------------------
__global__ void bconv_k(const float* __restrict__ w) {
    size_t i = (size_t)blockIdx.x * 256 + threadIdx.x;
    if (i >= (size_t)C_ * C_ * 9) return;
    int k = (int)(i % 9);
    size_t t = i / 9;
    int c = (int)(t % C_), o = (int)(t / C_);
    u16 h, l; split2(w[i], h, l);
    u16* dst = g_B1 + (size_t)o * KBIG + (size_t)k * 2304 + c;
    dst[0] = h; dst[768] = h; dst[1536] = l;       // slots [Bh, Bh, Bl]
}

__global__ void bfin_k(W10 ws) {
    size_t i = (size_t)blockIdx.x * 256 + threadIdx.x;
    if (i >= (size_t)5 * 512 * 1536) return;
    int cc = (int)(i % 1536);
    size_t t = i / 1536;
    int j = (int)(t % 512), b = (int)(t / 512);
    int half = cc / 768, c = cc % 768;
    const int CH[5] = {30, 100, 150, 220, 268};
    float v = 0.f;
    if (j < CH[b]) {
        if (half == 0) v = ws.a[b][j * C_ + c];
        else if (b >= 2) v = ws.b[b][j * C_ + c];
    }
    u16 h, l; split2(v, h, l);
    u16* dst = g_Bfin + ((size_t)b * 512 + j) * LDBF + half * 2304 + c;
    dst[0] = h; dst[768] = h; dst[1536] = l;
}

__global__ void bnprep_k(const float* g, const float* bt, const float* mu,
                         const float* var, const float* cb) {
    int c = blockIdx.x * 256 + threadIdx.x;
    if (c >= C_) return;
    float inv = g[c] / sqrtf(var[c] + 1e-5f);
    g_scale[c] = inv;
    g_shift[c] = cb[c] * inv + bt[c] - mu[c] * inv;
}

// ---------------- 2-seg split writer -----------------------------------------
__device__ __forceinline__ void store_split4_2seg(u32* base32, int tid, float4 v) {
    u16 h0, l0, h1, l1, h2, l2, h3, l3;
    split2(v.x, h0, l0); split2(v.y, h1, l1);
    split2(v.z, h2, l2); split2(v.w, h3, l3);
    base32[2 * tid]       = (u32)h0 | ((u32)h1 << 16);
    base32[2 * tid + 1]   = (u32)h2 | ((u32)h3 << 16);
    base32[384 + 2 * tid] = (u32)l0 | ((u32)l1 << 16);
    base32[385 + 2 * tid] = (u32)l2 | ((u32)l3 << 16);
}

__global__ void xsplit_k(X5 xs) {
    int row = blockIdx.x, b = blockIdx.y;
    float4 v = ((const float4*)(xs.p[b] + (size_t)row * C_))[threadIdx.x];
    u32* base32 = (u32*)(g_X2 + ((size_t)b * 4096 + row) * LDX);
    store_split4_2seg(base32, threadIdx.x, v);
}

// ---------------- offset / mask heads ----------------------------------------
__global__ void offsets_k(const float* __restrict__ ow, const float* __restrict__ mw) {
    int lane = threadIdx.x & 31;
    int row = blockIdx.x * 8 + (threadIdx.x >> 5);
    const float* omr = g_om + (size_t)row * C_;
    float v[24];
#pragma unroll
    for (int i = 0; i < 24; i++) v[i] = omr[lane + 32 * i];
    float res[27];
#pragma unroll
    for (int o = 0; o < 27; o++) {
        const float* wr = (o < 18) ? (ow + o * C_) : (mw + (o - 18) * C_);
        float s = 0.f;
#pragma unroll
        for (int i = 0; i < 24; i++) s += v[i] * wr[lane + 32 * i];
#pragma unroll
        for (int d = 16; d; d >>= 1) s += __shfl_xor_sync(0xffffffffu, s, d);
        res[o] = s;
    }
    if (lane == 0) {
        int z = row >> 10, p = row & 1023;
#pragma unroll
        for (int o = 0; o < 18; o++) g_off[z * 18 * P_ + o * P_ + p] = res[o];
        float mx = res[18];
#pragma unroll
        for (int k = 1; k < 9; k++) mx = fmaxf(mx, res[18 + k]);
        float e[9], sum = 0.f;
#pragma unroll
        for (int k = 0; k < 9; k++) { e[k] = expf(res[18 + k] - mx); sum += e[k]; }
        float r = 1.f / sum;
#pragma unroll
        for (int k = 0; k < 9; k++) g_mask[z * 9 * P_ + p * 9 + k] = e[k] * r;
    }
}

// ---------------- deformable sampling, 2-seg out -----------------------------
__global__ void sample_split_k(X5 xs) {
    int p = blockIdx.x, k = blockIdx.y, z = blockIdx.z;
    int b = z >> 2;
    float dy = g_off[z * 18 * P_ + (2 * k) * P_ + p];
    float dx = g_off[z * 18 * P_ + (2 * k + 1) * P_ + p];
    float m = g_mask[z * 9 * P_ + k * P_ + p];            // raw-reshape quirk
    int h = p >> 5, w = p & 31;
    float py = (float)(h - 1 + k / 3) + dy;
    float px = (float)(w - 1 + k % 3) + dx;
    float y0f = floorf(py), x0f = floorf(px);
    float wy = py - y0f, wx = px - x0f;
    int y0 = (int)y0f, x0 = (int)x0f;
    float w00 = (1.f - wy) * (1.f - wx), w01 = (1.f - wy) * wx;
    float w10 = wy * (1.f - wx),         w11 = wy * wx;
    bool vy0 = (y0 >= 0) && (y0 < 32),  vy1 = (y0 >= -1) && (y0 < 31);
    bool vx0 = (x0 >= 0) && (x0 < 32),  vx1 = (x0 >= -1) && (x0 < 31);
    const float4* xb = (const float4*)(xs.p[b] + (size_t)(z & 3) * P_ * C_);
    int t = threadIdx.x;
    float4 a = make_float4(0.f, 0.f, 0.f, 0.f);
    if (vy0 && vx0) { float4 s = xb[(size_t)(y0 * 32 + x0) * 192 + t];
        a.x += w00 * s.x; a.y += w00 * s.y; a.z += w00 * s.z; a.w += w00 * s.w; }
    if (vy0 && vx1) { float4 s = xb[(size_t)(y0 * 32 + x0 + 1) * 192 + t];
        a.x += w01 * s.x; a.y += w01 * s.y; a.z += w01 * s.z; a.w += w01 * s.w; }
    if (vy1 && vx0) { float4 s = xb[(size_t)((y0 + 1) * 32 + x0) * 192 + t];
        a.x += w10 * s.x; a.y += w10 * s.y; a.z += w10 * s.z; a.w += w10 * s.w; }
    if (vy1 && vx1) { float4 s = xb[(size_t)((y0 + 1) * 32 + x0 + 1) * 192 + t];
        a.x += w11 * s.x; a.y += w11 * s.y; a.z += w11 * s.z; a.w += w11 * s.w; }
    a.x *= m; a.y *= m; a.z *= m; a.w *= m;
    size_t row = (size_t)z * P_ + p;
    u32* base32 = (u32*)(g_A1 + row * LDA1 + (size_t)k * 1536);
    store_split4_2seg(base32, t, a);
}

// ---------------- mma.sync bf16 GEMM (all-cp.async A with slot remap) --------
// AK=1: A = im2col view of g_X2 (tap-shifted rows, zero-fill OOB) -> MODE 0
// AK=2: A = [g_blk | g_X2] halves (rows offset by bsel*4096)      -> MODE 2
// AK=3: A = g_A1 (sampled, 2-seg)                                 -> MODE 1
template<int AK, int MODE>
__global__ void __launch_bounds__(THREADS, 1) gemm_mma(
    const u16* __restrict__ Bg, long ldb, int NKin, X5 xs,
    const float* __restrict__ aux, float* __restrict__ outp, Fin fin)
{
    extern __shared__ char sm[];
    u32 sbase = s2u(sm);
    const int tid = threadIdx.x;
    const int wid = tid >> 5, lane = tid & 31;
    const int wm = wid >> 2, wn = wid & 3;
    const int m0 = blockIdx.y * TM, n0 = blockIdx.x * TN;

    int NK = NKin, chN = 0, coff = 0, bsel = 0;
    const u16* Bb0 = Bg;
    if (MODE == 2) {
        bsel = blockIdx.z;
        chN = fin.chN[bsel]; coff = fin.coff[bsel]; NK = fin.nk[bsel];
        Bb0 = Bg + (size_t)bsel * 512 * ldb;
        if (n0 >= chN) return;
    }
    const char* Bbase = (const char*)(Bb0 + (size_t)n0 * ldb);
    const long ldbb = ldb * 2;
    const int arow = tid >> 2, aq = tid & 3;      // 128 rows x 4 thr, 32B each

    // A-row in the 5-block-stacked scratch buffers
    int grow = m0 + (MODE == 2 ? bsel * 4096 : 0) + arow;
    int pbase = 0, ph = 0, pw = 0;
    if (AK == 1) {
        int p = grow & 1023;
        pbase = grow - p; ph = p >> 5; pw = p & 31;
    }

    auto loadStage = [&](int s, int kc) {
        u32 sb = sbase + s * STG_BYTES;
        u32 bb = sb + 16384;
        const char* Bgp = Bbase + (size_t)kc * 128;
#pragma unroll
        for (int it = 0; it < 4; it++) {
            int i = it * THREADS + tid;
            int row = i >> 3, c16 = i & 7;
            u32 off = (u32)(row * 128 + c16 * 16);
            cpa16(bb + SWZ(off), Bgp + (size_t)row * ldbb + c16 * 16);
        }
        // A: one K-chunk = (tap/half, slot, c0); 32B per thread as 2x16B
        u32 off = (u32)(arow * 128 + aq * 32);
        u32 d0 = sb + SWZ(off), d1 = sb + SWZ(off + 16);
        int elem = aq * 16;                        // u16 offset within chunk
        if (AK == 1) {
            int tap = kc / 36, rem = kc % 36;
            int slot = rem / 12, c0 = (rem % 12) << 6;
            int hh = ph + tap / 3 - 1, ww = pw + tap % 3 - 1;
            bool ok = hh >= 0 && hh < 32 && ww >= 0 && ww < 32;
            int srow = ok ? (pbase + (hh << 5) + ww) : 0;
            const u16* src = g_X2 + (size_t)srow * LDX +
                             (slot == 1 ? 768 : 0) + c0 + elem;
            u32 sz = ok ? 16u : 0u;
            cpa16z(d0, src, sz);
            cpa16z(d1, src + 8, sz);
        } else if (AK == 3) {
            int tap = kc / 36, rem = kc % 36;
            int slot = rem / 12, c0 = (rem % 12) << 6;
            const u16* src = g_A1 + (size_t)grow * LDA1 + tap * 1536 +
                             (slot == 1 ? 768 : 0) + c0 + elem;
            cpa16(d0, src);
            cpa16(d1, src + 8);
        } else {
            int half = kc / 36, rem = kc % 36;
            int slot = rem / 12, c0 = (rem % 12) << 6;
            const u16* base = half ? g_X2 : g_blk;
            const u16* src = base + (size_t)grow * LDX +
                             (slot == 1 ? 768 : 0) + c0 + elem;
            cpa16(d0, src);
            cpa16(d1, src + 8);
        }
        CP_COMMIT();
    };

    float acc[2][8][4];
#pragma unroll
    for (int i = 0; i < 2; i++)
#pragma unroll
        for (int j = 0; j < 8; j++)
#pragma unroll
            for (int q = 0; q < 4; q++) acc[i][j][q] = 0.f;

    loadStage(0, 0);
    loadStage(1, 1);

    for (int kc = 0; kc < NK; kc++) {
        CP_WAIT1();
        __syncthreads();
        u32 ab = sbase + (kc % 3) * STG_BYTES;
        u32 bb = ab + 16384;
#pragma unroll
        for (int ks = 0; ks < 4; ks++) {
            u32 afr[2][4];
#pragma unroll
            for (int ms = 0; ms < 2; ms++) {
                int row = wm * 32 + ms * 16 + (lane & 15);
                u32 off = (u32)(row * 128 + ks * 32 + (lane >> 4) * 16);
                LDSM4(afr[ms][0], afr[ms][1], afr[ms][2], afr[ms][3], ab + SWZ(off));
            }
#pragma unroll
            for (int np = 0; np < 4; np++) {
                int g = lane >> 3;
                int row = wn * 64 + np * 16 + ((g >> 1) & 1) * 8 + (lane & 7);
                u32 off = (u32)(row * 128 + ks * 32 + (g & 1) * 16);
                u32 bfr[4];
                LDSM4(bfr[0], bfr[1], bfr[2], bfr[3], bb + SWZ(off));
#pragma unroll
                for (int ms = 0; ms < 2; ms++) {
                    MMA16816(acc[ms][2 * np], afr[ms][0], afr[ms][1], afr[ms][2],
                             afr[ms][3], bfr[0], bfr[1]);
                    MMA16816(acc[ms][2 * np + 1], afr[ms][0], afr[ms][1], afr[ms][2],
                             afr[ms][3], bfr[2], bfr[3]);
                }
            }
        }
        __syncthreads();
        int kl = kc + 2;
        if (kl < NK) loadStage(kl % 3, kl);
        else CP_COMMIT();
    }

    // epilogue
    int quad = lane >> 2, qt = lane & 3;
#pragma unroll
    for (int ms = 0; ms < 2; ms++) {
#pragma unroll
        for (int ns = 0; ns < 8; ns++) {
            int colb = n0 + wn * 64 + ns * 8 + 2 * qt;
#pragma unroll
            for (int hh = 0; hh < 2; hh++) {
                int row = m0 + wm * 32 + ms * 16 + quad + hh * 8;
                float v0 = acc[ms][ns][2 * hh], v1 = acc[ms][ns][2 * hh + 1];
                if (MODE == 0) {
                    g_om[(size_t)row * C_ + colb]     = v0 + aux[colb];
                    g_om[(size_t)row * C_ + colb + 1] = v1 + aux[colb + 1];
                } else if (MODE == 1) {
                    float t0 = fmaxf(v0 * g_scale[colb] + g_shift[colb], 0.f);
                    float t1 = fmaxf(v1 * g_scale[colb + 1] + g_shift[colb + 1], 0.f);
                    u16 h0, l0, h1, l1;
                    split2(t0, h0, l0); split2(t1, h1, l1);
                    u32* p32 = (u32*)(g_blk + (size_t)row * LDX);
                    int ci = colb >> 1;
                    p32[ci]       = (u32)h0 | ((u32)h1 << 16);
                    p32[384 + ci] = (u32)l0 | ((u32)l1 << 16);
                } else {
                    // output/residual rows are the plain 4096 spatial rows:
                    // concat is along channels, NOT rows (bug fixed from R6)
                    if (colb < chN)
                        outp[(size_t)row * C_ + coff + colb] =
                            v0 + aux[(size_t)row * C_ + coff + colb];
                    if (colb + 1 < chN)
                        outp[(size_t)row * C_ + coff + colb + 1] =
                            v1 + aux[(size_t)row * C_ + coff + colb + 1];
                }
            }
        }
    }
}

// ---------------- launch -----------------------------------------------------
extern "C" void kernel_launch(void* const* d_in, const int* in_sizes, int n_in,
                              void* d_out, int out_size) {
    static u16 *pB1 = 0, *pBf = 0;
    if (!pB1) {
        cudaGetSymbolAddress((void**)&pB1, g_B1);
        cudaGetSymbolAddress((void**)&pBf, g_Bfin);
        cudaFuncSetAttribute(gemm_mma<1, 0>,
                             cudaFuncAttributeMaxDynamicSharedMemorySize, DYN_SMEM);
        cudaFuncSetAttribute(gemm_mma<3, 1>,
                             cudaFuncAttributeMaxDynamicSharedMemorySize, DYN_SMEM);
        cudaFuncSetAttribute(gemm_mma<2, 2>,
                             cudaFuncAttributeMaxDynamicSharedMemorySize, DYN_SMEM);
    }
    X5 xs;
    for (int i = 0; i < 5; i++) xs.p[i] = (const float*)d_in[i];
    const float* conv_w = (const float*)d_in[5];
    const float* conv_b = (const float*)d_in[6];
    const float* offw   = (const float*)d_in[7];
    const float* maskw  = (const float*)d_in[8];
    W10 ws;
    const int waIdx[5] = {0, 1, 2, 4, 6};
    for (int b = 0; b < 5; b++) {
        ws.a[b] = (const float*)d_in[13 + waIdx[b]];
        ws.b[b] = (b >= 2) ? (const float*)d_in[13 + waIdx[b] + 1] : ws.a[b];
    }
    float* out = (float*)d_out;
    Fin fin;
    const int CH[5]   = {30, 100, 150, 220, 268};
    const int COFF[5] = {0, 30, 130, 280, 500};
    for (int b = 0; b < 5; b++) {
        fin.chN[b] = CH[b]; fin.coff[b] = COFF[b]; fin.nk[b] = (b < 2) ? 36 : 72;
    }

    bconv_k<<<(int)(((size_t)C_ * C_ * 9 + 255) / 256), 256>>>(conv_w);
    bfin_k<<<(int)(((size_t)5 * 512 * 1536 + 255) / 256), 256>>>(ws);
    bnprep_k<<<3, 256>>>((const float*)d_in[9], (const float*)d_in[10],
                         (const float*)d_in[11], (const float*)d_in[12], conv_b);
    xsplit_k<<<dim3(4096, 5), 192>>>(xs);

    gemm_mma<1, 0><<<dim3(3, 160), THREADS, DYN_SMEM>>>(
        pB1, KBIG, 324, xs, conv_b, nullptr, fin);
    offsets_k<<<2560, 256>>>(offw, maskw);
    sample_split_k<<<dim3(P_, 9, 20), 192>>>(xs);
    gemm_mma<3, 1><<<dim3(3, 160), THREADS, DYN_SMEM>>>(
        pB1, KBIG, 324, xs, nullptr, nullptr, fin);
    gemm_mma<2, 2><<<dim3(2, 32, 5), THREADS, DYN_SMEM>>>(
        pBf, LDBF, 0, xs, xs.p[4], out, fin);
}

// round 8
// speedup vs baseline: 2.0212x; 1.3722x over previous
#include <cuda_runtime.h>
#include <cuda_fp16.h>
#include <math.h>
#include <stdint.h>

typedef unsigned short u16;
typedef uint32_t u32;
typedef uint64_t u64;

#define C_    768
#define P_    1024
#define LDA1  13824          // sampled A phys row: 9 taps x [hi|lo] x 768 (fp16)
#define LDX   1536           // g_X2 / g_blk phys row: [hi 768 | lo 768]
#define LDB1  6912           // conv weight row: 9 taps x 768, hi-only
#define LDBF  1536           // 1x1 weight row: 2 halves x 768, hi-only
#define MBIG  20480
#define TM    128
#define TN    256
#define THREADS 512
#define STG_BYTES 49152      // A 16KB + B 32KB
#define DYN_SMEM (3 * STG_BYTES)

// ---------------- static device scratch --------------------------------------
__device__ u16  g_X2[(size_t)MBIG * LDX];          // split inputs (all 5 blocks)
__device__ u16  g_blk[(size_t)MBIG * LDX];         // split block outputs
__device__ u16  g_A1[(size_t)MBIG * LDA1];         // split sampled A
__device__ u16  g_B1[(size_t)C_ * LDB1];           // conv weights hi-only
__device__ u16  g_Bfin[(size_t)5 * 512 * LDBF];    // 1x1 weights hi-only padded
__device__ float g_om[(size_t)MBIG * C_];
__device__ float g_off[20 * 18 * P_];
__device__ float g_mask[20 * 9 * P_];
__device__ float g_scale[C_], g_shift[C_];

struct X5  { const float* p[5]; };
struct W10 { const float* a[5]; const float* b[5]; };
struct Fin { int chN[5]; int coff[5]; int nk[5]; };

// ---------------- helpers ----------------------------------------------------
__device__ __forceinline__ void split2h(float v, u16& h, u16& l) {
    __half hb = __float2half_rn(v);
    h = __half_as_ushort(hb);
    l = __half_as_ushort(__float2half_rn(v - __half2float(hb)));
}
__device__ __forceinline__ u32 s2u(const void* p) {
    return (u32)__cvta_generic_to_shared(p);
}
__device__ __forceinline__ void cpa16(u32 s, const void* g) {
    asm volatile("cp.async.cg.shared.global [%0], [%1], 16;"
                 :: "r"(s), "l"((u64)__cvta_generic_to_global((void*)g)));
}
__device__ __forceinline__ void cpa16z(u32 s, const void* g, u32 sz) {
    asm volatile("cp.async.cg.shared.global [%0], [%1], 16, %2;"
                 :: "r"(s), "l"((u64)__cvta_generic_to_global((void*)g)), "r"(sz));
}
#define CP_COMMIT() asm volatile("cp.async.commit_group;")
#define CP_WAIT1()  asm volatile("cp.async.wait_group 1;")
#define SWZ(o) ((o) ^ (((o) >> 3) & 0x70))
#define LDSM4(r0, r1, r2, r3, addr) \
    asm volatile("ldmatrix.sync.aligned.m8n8.x4.shared.b16 {%0,%1,%2,%3}, [%4];" \
        : "=r"(r0), "=r"(r1), "=r"(r2), "=r"(r3) : "r"(addr))
#define MMA16816(d, a0, a1, a2, a3, b0, b1) \
    asm volatile("mma.sync.aligned.m16n8k16.row.col.f32.f16.f16.f32 " \
        "{%0,%1,%2,%3}, {%4,%5,%6,%7}, {%8,%9}, {%0,%1,%2,%3};" \
        : "+f"((d)[0]), "+f"((d)[1]), "+f"((d)[2]), "+f"((d)[3]) \
        : "r"(a0), "r"(a1), "r"(a2), "r"(a3), "r"(b0), "r"(b1))

// ---------------- weight / BN prep -------------------------------------------
__global__ void bconv_k(const float* __restrict__ w) {
    size_t i = (size_t)blockIdx.x * 256 + threadIdx.x;
    if (i >= (size_t)C_ * C_ * 9) return;
    int k = (int)(i % 9);
    size_t t = i / 9;
    int c = (int)(t % C_), o = (int)(t / C_);
    g_B1[(size_t)o * LDB1 + k * C_ + c] =
        __half_as_ushort(__float2half_rn(w[i]));
}

__global__ void bfin_k(W10 ws) {
    size_t i = (size_t)blockIdx.x * 256 + threadIdx.x;
    if (i >= (size_t)5 * 512 * 1536) return;
    int cc = (int)(i % 1536);
    size_t t = i / 1536;
    int j = (int)(t % 512), b = (int)(t / 512);
    int half = cc / 768, c = cc % 768;
    const int CH[5] = {30, 100, 150, 220, 268};
    float v = 0.f;
    if (j < CH[b]) {
        if (half == 0) v = ws.a[b][j * C_ + c];
        else if (b >= 2) v = ws.b[b][j * C_ + c];
    }
    g_Bfin[((size_t)b * 512 + j) * LDBF + cc] =
        __half_as_ushort(__float2half_rn(v));
}

__global__ void bnprep_k(const float* g, const float* bt, const float* mu,
                         const float* var, const float* cb) {
    int c = blockIdx.x * 256 + threadIdx.x;
    if (c >= C_) return;
    float inv = g[c] / sqrtf(var[c] + 1e-5f);
    g_scale[c] = inv;
    g_shift[c] = cb[c] * inv + bt[c] - mu[c] * inv;
}

// ---------------- 2-seg split writer -----------------------------------------
__device__ __forceinline__ void store_split4_2seg(u32* base32, int tid, float4 v) {
    u16 h0, l0, h1, l1, h2, l2, h3, l3;
    split2h(v.x, h0, l0); split2h(v.y, h1, l1);
    split2h(v.z, h2, l2); split2h(v.w, h3, l3);
    base32[2 * tid]       = (u32)h0 | ((u32)h1 << 16);
    base32[2 * tid + 1]   = (u32)h2 | ((u32)h3 << 16);
    base32[384 + 2 * tid] = (u32)l0 | ((u32)l1 << 16);
    base32[385 + 2 * tid] = (u32)l2 | ((u32)l3 << 16);
}

__global__ void xsplit_k(X5 xs) {
    int row = blockIdx.x, b = blockIdx.y;
    float4 v = ((const float4*)(xs.p[b] + (size_t)row * C_))[threadIdx.x];
    u32* base32 = (u32*)(g_X2 + ((size_t)b * 4096 + row) * LDX);
    store_split4_2seg(base32, threadIdx.x, v);
}

// ---------------- offset / mask heads ----------------------------------------
__global__ void offsets_k(const float* __restrict__ ow, const float* __restrict__ mw) {
    int lane = threadIdx.x & 31;
    int row = blockIdx.x * 8 + (threadIdx.x >> 5);
    const float* omr = g_om + (size_t)row * C_;
    float v[24];
#pragma unroll
    for (int i = 0; i < 24; i++) v[i] = omr[lane + 32 * i];
    float res[27];
#pragma unroll
    for (int o = 0; o < 27; o++) {
        const float* wr = (o < 18) ? (ow + o * C_) : (mw + (o - 18) * C_);
        float s = 0.f;
#pragma unroll
        for (int i = 0; i < 24; i++) s += v[i] * wr[lane + 32 * i];
#pragma unroll
        for (int d = 16; d; d >>= 1) s += __shfl_xor_sync(0xffffffffu, s, d);
        res[o] = s;
    }
    if (lane == 0) {
        int z = row >> 10, p = row & 1023;
#pragma unroll
        for (int o = 0; o < 18; o++) g_off[z * 18 * P_ + o * P_ + p] = res[o];
        float mx = res[18];
#pragma unroll
        for (int k = 1; k < 9; k++) mx = fmaxf(mx, res[18 + k]);
        float e[9], sum = 0.f;
#pragma unroll
        for (int k = 0; k < 9; k++) { e[k] = expf(res[18 + k] - mx); sum += e[k]; }
        float r = 1.f / sum;
#pragma unroll
        for (int k = 0; k < 9; k++) g_mask[z * 9 * P_ + p * 9 + k] = e[k] * r;
    }
}

// ---------------- deformable sampling, 2-seg out -----------------------------
__global__ void sample_split_k(X5 xs) {
    int p = blockIdx.x, k = blockIdx.y, z = blockIdx.z;
    int b = z >> 2;
    float dy = g_off[z * 18 * P_ + (2 * k) * P_ + p];
    float dx = g_off[z * 18 * P_ + (2 * k + 1) * P_ + p];
    float m = g_mask[z * 9 * P_ + k * P_ + p];            // raw-reshape quirk
    int h = p >> 5, w = p & 31;
    float py = (float)(h - 1 + k / 3) + dy;
    float px = (float)(w - 1 + k % 3) + dx;
    float y0f = floorf(py), x0f = floorf(px);
    float wy = py - y0f, wx = px - x0f;
    int y0 = (int)y0f, x0 = (int)x0f;
    float w00 = (1.f - wy) * (1.f - wx), w01 = (1.f - wy) * wx;
    float w10 = wy * (1.f - wx),         w11 = wy * wx;
    bool vy0 = (y0 >= 0) && (y0 < 32),  vy1 = (y0 >= -1) && (y0 < 31);
    bool vx0 = (x0 >= 0) && (x0 < 32),  vx1 = (x0 >= -1) && (x0 < 31);
    const float4* xb = (const float4*)(xs.p[b] + (size_t)(z & 3) * P_ * C_);
    int t = threadIdx.x;
    float4 a = make_float4(0.f, 0.f, 0.f, 0.f);
    if (vy0 && vx0) { float4 s = xb[(size_t)(y0 * 32 + x0) * 192 + t];
        a.x += w00 * s.x; a.y += w00 * s.y; a.z += w00 * s.z; a.w += w00 * s.w; }
    if (vy0 && vx1) { float4 s = xb[(size_t)(y0 * 32 + x0 + 1) * 192 + t];
        a.x += w01 * s.x; a.y += w01 * s.y; a.z += w01 * s.z; a.w += w01 * s.w; }
    if (vy1 && vx0) { float4 s = xb[(size_t)((y0 + 1) * 32 + x0) * 192 + t];
        a.x += w10 * s.x; a.y += w10 * s.y; a.z += w10 * s.z; a.w += w10 * s.w; }
    if (vy1 && vx1) { float4 s = xb[(size_t)((y0 + 1) * 32 + x0 + 1) * 192 + t];
        a.x += w11 * s.x; a.y += w11 * s.y; a.z += w11 * s.z; a.w += w11 * s.w; }
    a.x *= m; a.y *= m; a.z *= m; a.w *= m;
    size_t row = (size_t)z * P_ + p;
    u32* base32 = (u32*)(g_A1 + row * LDA1 + (size_t)k * 1536);
    store_split4_2seg(base32, t, a);
}

// ---------------- mma.sync fp16 GEMM (2-slot split: A=[Ah,Al], B=[Bh,Bh]) ----
// Per K-chunk kc: seg = kc/24 (tap or half), slot = (kc%24)/12, c0 = (kc%12)*64
// A slot0 -> hi segment, slot1 -> lo segment; B always hi (slot-independent).
// AK=1: A = im2col view of g_X2 (zero-fill OOB)  -> MODE 0 (NK=216)
// AK=2: A = [g_blk | g_X2] halves                -> MODE 2 (NK=24/48)
// AK=3: A = g_A1 (sampled)                       -> MODE 1 (NK=216)
template<int AK, int MODE>
__global__ void __launch_bounds__(THREADS, 1) gemm_mma(
    const u16* __restrict__ Bg, long ldb, int NKin, X5 xs,
    const float* __restrict__ aux, float* __restrict__ outp, Fin fin)
{
    extern __shared__ char sm[];
    u32 sbase = s2u(sm);
    const int tid = threadIdx.x;
    const int wid = tid >> 5, lane = tid & 31;
    const int wm = wid >> 2, wn = wid & 3;
    const int m0 = blockIdx.y * TM, n0 = blockIdx.x * TN;

    int NK = NKin, chN = 0, coff = 0, bsel = 0;
    const u16* Bb0 = Bg;
    if (MODE == 2) {
        bsel = blockIdx.z;
        chN = fin.chN[bsel]; coff = fin.coff[bsel]; NK = fin.nk[bsel];
        Bb0 = Bg + (size_t)bsel * 512 * ldb;
        if (n0 >= chN) return;
    }
    const char* Bbase = (const char*)(Bb0 + (size_t)n0 * ldb);
    const long ldbb = ldb * 2;
    const int arow = tid >> 2, aq = tid & 3;      // 128 rows x 4 thr, 32B each

    // A-row in the 5-block-stacked scratch buffers
    int grow = m0 + (MODE == 2 ? bsel * 4096 : 0) + arow;
    int pbase = 0, ph = 0, pw = 0;
    if (AK == 1) {
        int p = grow & 1023;
        pbase = grow - p; ph = p >> 5; pw = p & 31;
    }

    auto loadStage = [&](int s, int kc) {
        u32 sb = sbase + s * STG_BYTES;
        u32 bb = sb + 16384;
        int seg = kc / 24, rem = kc % 24;
        int slot = rem / 12, c0 = (rem % 12) << 6;
        // B: hi-only, slot-independent
        const char* Bgp = Bbase + (size_t)(seg * C_ + c0) * 2;
#pragma unroll
        for (int it = 0; it < 4; it++) {
            int i = it * THREADS + tid;
            int row = i >> 3, c16 = i & 7;
            u32 off = (u32)(row * 128 + c16 * 16);
            cpa16(bb + SWZ(off), Bgp + (size_t)row * ldbb + c16 * 16);
        }
        // A: 32B per thread as 2x16B
        u32 off = (u32)(arow * 128 + aq * 32);
        u32 d0 = sb + SWZ(off), d1 = sb + SWZ(off + 16);
        int elem = aq * 16;
        int soff = slot * C_ + c0 + elem;
        if (AK == 1) {
            int hh = ph + seg / 3 - 1, ww = pw + seg % 3 - 1;
            bool ok = hh >= 0 && hh < 32 && ww >= 0 && ww < 32;
            int srow = ok ? (pbase + (hh << 5) + ww) : 0;
            const u16* src = g_X2 + (size_t)srow * LDX + soff;
            u32 sz = ok ? 16u : 0u;
            cpa16z(d0, src, sz);
            cpa16z(d1, src + 8, sz);
        } else if (AK == 3) {
            const u16* src = g_A1 + (size_t)grow * LDA1 + seg * 1536 + soff;
            cpa16(d0, src);
            cpa16(d1, src + 8);
        } else {
            const u16* base = seg ? g_X2 : g_blk;
            const u16* src = base + (size_t)grow * LDX + soff;
            cpa16(d0, src);
            cpa16(d1, src + 8);
        }
        CP_COMMIT();
    };

    float acc[2][8][4];
#pragma unroll
    for (int i = 0; i < 2; i++)
#pragma unroll
        for (int j = 0; j < 8; j++)
#pragma unroll
            for (int q = 0; q < 4; q++) acc[i][j][q] = 0.f;

    loadStage(0, 0);
    loadStage(1, 1);

    for (int kc = 0; kc < NK; kc++) {
        CP_WAIT1();
        __syncthreads();
        u32 ab = sbase + (kc % 3) * STG_BYTES;
        u32 bb = ab + 16384;
#pragma unroll
        for (int ks = 0; ks < 4; ks++) {
            u32 afr[2][4];
#pragma unroll
            for (int ms = 0; ms < 2; ms++) {
                int row = wm * 32 + ms * 16 + (lane & 15);
                u32 off = (u32)(row * 128 + ks * 32 + (lane >> 4) * 16);
                LDSM4(afr[ms][0], afr[ms][1], afr[ms][2], afr[ms][3], ab + SWZ(off));
            }
#pragma unroll
            for (int np = 0; np < 4; np++) {
                int g = lane >> 3;
                int row = wn * 64 + np * 16 + ((g >> 1) & 1) * 8 + (lane & 7);
                u32 off = (u32)(row * 128 + ks * 32 + (g & 1) * 16);
                u32 bfr[4];
                LDSM4(bfr[0], bfr[1], bfr[2], bfr[3], bb + SWZ(off));
#pragma unroll
                for (int ms = 0; ms < 2; ms++) {
                    MMA16816(acc[ms][2 * np], afr[ms][0], afr[ms][1], afr[ms][2],
                             afr[ms][3], bfr[0], bfr[1]);
                    MMA16816(acc[ms][2 * np + 1], afr[ms][0], afr[ms][1], afr[ms][2],
                             afr[ms][3], bfr[2], bfr[3]);
                }
            }
        }
        __syncthreads();
        int kl = kc + 2;
        if (kl < NK) loadStage(kl % 3, kl);
        else CP_COMMIT();
    }

    // epilogue
    int quad = lane >> 2, qt = lane & 3;
#pragma unroll
    for (int ms = 0; ms < 2; ms++) {
#pragma unroll
        for (int ns = 0; ns < 8; ns++) {
            int colb = n0 + wn * 64 + ns * 8 + 2 * qt;
#pragma unroll
            for (int hh = 0; hh < 2; hh++) {
                int row = m0 + wm * 32 + ms * 16 + quad + hh * 8;
                float v0 = acc[ms][ns][2 * hh], v1 = acc[ms][ns][2 * hh + 1];
                if (MODE == 0) {
                    g_om[(size_t)row * C_ + colb]     = v0 + aux[colb];
                    g_om[(size_t)row * C_ + colb + 1] = v1 + aux[colb + 1];
                } else if (MODE == 1) {
                    float t0 = fmaxf(v0 * g_scale[colb] + g_shift[colb], 0.f);
                    float t1 = fmaxf(v1 * g_scale[colb + 1] + g_shift[colb + 1], 0.f);
                    u16 h0, l0, h1, l1;
                    split2h(t0, h0, l0); split2h(t1, h1, l1);
                    u32* p32 = (u32*)(g_blk + (size_t)row * LDX);
                    int ci = colb >> 1;
                    p32[ci]       = (u32)h0 | ((u32)h1 << 16);
                    p32[384 + ci] = (u32)l0 | ((u32)l1 << 16);
                } else {
                    // concat is along channels: plain 4096 spatial rows
                    if (colb < chN)
                        outp[(size_t)row * C_ + coff + colb] =
                            v0 + aux[(size_t)row * C_ + coff + colb];
                    if (colb + 1 < chN)
                        outp[(size_t)row * C_ + coff + colb + 1] =
                            v1 + aux[(size_t)row * C_ + coff + colb + 1];
                }
            }
        }
    }
}

// ---------------- launch -----------------------------------------------------
extern "C" void kernel_launch(void* const* d_in, const int* in_sizes, int n_in,
                              void* d_out, int out_size) {
    static u16 *pB1 = 0, *pBf = 0;
    if (!pB1) {
        cudaGetSymbolAddress((void**)&pB1, g_B1);
        cudaGetSymbolAddress((void**)&pBf, g_Bfin);
        cudaFuncSetAttribute(gemm_mma<1, 0>,
                             cudaFuncAttributeMaxDynamicSharedMemorySize, DYN_SMEM);
        cudaFuncSetAttribute(gemm_mma<3, 1>,
                             cudaFuncAttributeMaxDynamicSharedMemorySize, DYN_SMEM);
        cudaFuncSetAttribute(gemm_mma<2, 2>,
                             cudaFuncAttributeMaxDynamicSharedMemorySize, DYN_SMEM);
    }
    X5 xs;
    for (int i = 0; i < 5; i++) xs.p[i] = (const float*)d_in[i];
    const float* conv_w = (const float*)d_in[5];
    const float* conv_b = (const float*)d_in[6];
    const float* offw   = (const float*)d_in[7];
    const float* maskw  = (const float*)d_in[8];
    W10 ws;
    const int waIdx[5] = {0, 1, 2, 4, 6};
    for (int b = 0; b < 5; b++) {
        ws.a[b] = (const float*)d_in[13 + waIdx[b]];
        ws.b[b] = (b >= 2) ? (const float*)d_in[13 + waIdx[b] + 1] : ws.a[b];
    }
    float* out = (float*)d_out;
    Fin fin;
    const int CH[5]   = {30, 100, 150, 220, 268};
    const int COFF[5] = {0, 30, 130, 280, 500};
    for (int b = 0; b < 5; b++) {
        fin.chN[b] = CH[b]; fin.coff[b] = COFF[b]; fin.nk[b] = (b < 2) ? 24 : 48;
    }

    bconv_k<<<(int)(((size_t)C_ * C_ * 9 + 255) / 256), 256>>>(conv_w);
    bfin_k<<<(int)(((size_t)5 * 512 * 1536 + 255) / 256), 256>>>(ws);
    bnprep_k<<<3, 256>>>((const float*)d_in[9], (const float*)d_in[10],
                         (const float*)d_in[11], (const float*)d_in[12], conv_b);
    xsplit_k<<<dim3(4096, 5), 192>>>(xs);

    gemm_mma<1, 0><<<dim3(3, 160), THREADS, DYN_SMEM>>>(
        pB1, LDB1, 216, xs, conv_b, nullptr, fin);
    offsets_k<<<2560, 256>>>(offw, maskw);
    sample_split_k<<<dim3(P_, 9, 20), 192>>>(xs);
    gemm_mma<3, 1><<<dim3(3, 160), THREADS, DYN_SMEM>>>(
        pB1, LDB1, 216, xs, nullptr, nullptr, fin);
    gemm_mma<2, 2><<<dim3(2, 32, 5), THREADS, DYN_SMEM>>>(
        pBf, LDBF, 0, xs, xs.p[4], out, fin);
}

// round 9
// speedup vs baseline: 2.5683x; 1.2707x over previous
#include <cuda_runtime.h>
#include <cuda_fp16.h>
#include <math.h>
#include <stdint.h>

typedef unsigned short u16;
typedef uint32_t u32;
typedef uint64_t u64;

#define C_    768
#define P_    1024
#define LDA1  13824          // sampled A phys row: 9 taps x [hi|lo] x 768 (fp16)
#define LDX   1536           // g_X2 / g_blk phys row: [hi 768 | lo 768]
#define LDB1  6912           // conv weight row: 9 taps x 768, hi-only
#define LDBF  1536           // 1x1 weight row: 2 halves x 768, hi-only
#define MBIG  20480
#define TM    128
#define TN    256
#define THREADS 512
#define STG_BYTES 49152      // A 16KB + B 32KB
#define DYN_SMEM (3 * STG_BYTES)

// ---------------- static device scratch --------------------------------------
__device__ u16  g_X2[(size_t)MBIG * LDX];          // split inputs (all 5 blocks)
__device__ u16  g_blk[(size_t)MBIG * LDX];         // split block outputs
__device__ u16  g_A1[(size_t)MBIG * LDA1];         // split sampled A
__device__ u16  g_B1[(size_t)C_ * LDB1];           // conv weights hi-only
__device__ u16  g_Bfin[(size_t)5 * 512 * LDBF];    // 1x1 weights hi-only padded
__device__ float g_om[(size_t)MBIG * C_];
__device__ float g_off[20 * 18 * P_];
__device__ float g_mask[20 * 9 * P_];
__device__ float g_scale[C_], g_shift[C_];

struct X5  { const float* p[5]; };
struct W10 { const float* a[5]; const float* b[5]; };
struct Fin { int chN[5]; int coff[5]; int nk[5]; };

// ---------------- helpers ----------------------------------------------------
__device__ __forceinline__ void split2h(float v, u16& h, u16& l) {
    __half hb = __float2half_rn(v);
    h = __half_as_ushort(hb);
    l = __half_as_ushort(__float2half_rn(v - __half2float(hb)));
}
__device__ __forceinline__ u32 s2u(const void* p) {
    return (u32)__cvta_generic_to_shared(p);
}
__device__ __forceinline__ void cpa16(u32 s, const void* g) {
    asm volatile("cp.async.cg.shared.global [%0], [%1], 16;"
                 :: "r"(s), "l"((u64)__cvta_generic_to_global((void*)g)));
}
__device__ __forceinline__ void cpa16z(u32 s, const void* g, u32 sz) {
    asm volatile("cp.async.cg.shared.global [%0], [%1], 16, %2;"
                 :: "r"(s), "l"((u64)__cvta_generic_to_global((void*)g)), "r"(sz));
}
#define CP_COMMIT() asm volatile("cp.async.commit_group;")
#define CP_WAIT1()  asm volatile("cp.async.wait_group 1;")
#define SWZ(o) ((o) ^ (((o) >> 3) & 0x70))
#define LDSM4(r0, r1, r2, r3, addr) \
    asm volatile("ldmatrix.sync.aligned.m8n8.x4.shared.b16 {%0,%1,%2,%3}, [%4];" \
        : "=r"(r0), "=r"(r1), "=r"(r2), "=r"(r3) : "r"(addr))
#define MMA16816(d, a0, a1, a2, a3, b0, b1) \
    asm volatile("mma.sync.aligned.m16n8k16.row.col.f32.f16.f16.f32 " \
        "{%0,%1,%2,%3}, {%4,%5,%6,%7}, {%8,%9}, {%0,%1,%2,%3};" \
        : "+f"((d)[0]), "+f"((d)[1]), "+f"((d)[2]), "+f"((d)[3]) \
        : "r"(a0), "r"(a1), "r"(a2), "r"(a3), "r"(b0), "r"(b1))

// ---------------- weight / BN prep -------------------------------------------
__global__ void bconv_k(const float* __restrict__ w) {
    size_t i = (size_t)blockIdx.x * 256 + threadIdx.x;
    if (i >= (size_t)C_ * C_ * 9) return;
    int k = (int)(i % 9);
    size_t t = i / 9;
    int c = (int)(t % C_), o = (int)(t / C_);
    g_B1[(size_t)o * LDB1 + k * C_ + c] =
        __half_as_ushort(__float2half_rn(w[i]));
}

__global__ void bfin_k(W10 ws) {
    size_t i = (size_t)blockIdx.x * 256 + threadIdx.x;
    if (i >= (size_t)5 * 512 * 1536) return;
    int cc = (int)(i % 1536);
    size_t t = i / 1536;
    int j = (int)(t % 512), b = (int)(t / 512);
    int half = cc / 768, c = cc % 768;
    const int CH[5] = {30, 100, 150, 220, 268};
    float v = 0.f;
    if (j < CH[b]) {
        if (half == 0) v = ws.a[b][j * C_ + c];
        else if (b >= 2) v = ws.b[b][j * C_ + c];
    }
    g_Bfin[((size_t)b * 512 + j) * LDBF + cc] =
        __half_as_ushort(__float2half_rn(v));
}

__global__ void bnprep_k(const float* g, const float* bt, const float* mu,
                         const float* var, const float* cb) {
    int c = blockIdx.x * 256 + threadIdx.x;
    if (c >= C_) return;
    float inv = g[c] / sqrtf(var[c] + 1e-5f);
    g_scale[c] = inv;
    g_shift[c] = cb[c] * inv + bt[c] - mu[c] * inv;
}

// ---------------- 2-seg split writer -----------------------------------------
__device__ __forceinline__ void store_split4_2seg(u32* base32, int tid, float4 v) {
    u16 h0, l0, h1, l1, h2, l2, h3, l3;
    split2h(v.x, h0, l0); split2h(v.y, h1, l1);
    split2h(v.z, h2, l2); split2h(v.w, h3, l3);
    base32[2 * tid]       = (u32)h0 | ((u32)h1 << 16);
    base32[2 * tid + 1]   = (u32)h2 | ((u32)h3 << 16);
    base32[384 + 2 * tid] = (u32)l0 | ((u32)l1 << 16);
    base32[385 + 2 * tid] = (u32)l2 | ((u32)l3 << 16);
}

__global__ void xsplit_k(X5 xs) {
    int row = blockIdx.x, b = blockIdx.y;
    float4 v = ((const float4*)(xs.p[b] + (size_t)row * C_))[threadIdx.x];
    u32* base32 = (u32*)(g_X2 + ((size_t)b * 4096 + row) * LDX);
    store_split4_2seg(base32, threadIdx.x, v);
}

// ---------------- offset / mask heads ----------------------------------------
__global__ void offsets_k(const float* __restrict__ ow, const float* __restrict__ mw) {
    int lane = threadIdx.x & 31;
    int row = blockIdx.x * 8 + (threadIdx.x >> 5);
    const float* omr = g_om + (size_t)row * C_;
    float v[24];
#pragma unroll
    for (int i = 0; i < 24; i++) v[i] = omr[lane + 32 * i];
    float res[27];
#pragma unroll
    for (int o = 0; o < 27; o++) {
        const float* wr = (o < 18) ? (ow + o * C_) : (mw + (o - 18) * C_);
        float s = 0.f;
#pragma unroll
        for (int i = 0; i < 24; i++) s += v[i] * wr[lane + 32 * i];
#pragma unroll
        for (int d = 16; d; d >>= 1) s += __shfl_xor_sync(0xffffffffu, s, d);
        res[o] = s;
    }
    if (lane == 0) {
        int z = row >> 10, p = row & 1023;
#pragma unroll
        for (int o = 0; o < 18; o++) g_off[z * 18 * P_ + o * P_ + p] = res[o];
        float mx = res[18];
#pragma unroll
        for (int k = 1; k < 9; k++) mx = fmaxf(mx, res[18 + k]);
        float e[9], sum = 0.f;
#pragma unroll
        for (int k = 0; k < 9; k++) { e[k] = expf(res[18 + k] - mx); sum += e[k]; }
        float r = 1.f / sum;
#pragma unroll
        for (int k = 0; k < 9; k++) g_mask[z * 9 * P_ + p * 9 + k] = e[k] * r;
    }
}

// ---------------- deformable sampling, 2-seg out -----------------------------
__global__ void sample_split_k(X5 xs) {
    int p = blockIdx.x, k = blockIdx.y, z = blockIdx.z;
    int b = z >> 2;
    float dy = g_off[z * 18 * P_ + (2 * k) * P_ + p];
    float dx = g_off[z * 18 * P_ + (2 * k + 1) * P_ + p];
    float m = g_mask[z * 9 * P_ + k * P_ + p];            // raw-reshape quirk
    int h = p >> 5, w = p & 31;
    float py = (float)(h - 1 + k / 3) + dy;
    float px = (float)(w - 1 + k % 3) + dx;
    float y0f = floorf(py), x0f = floorf(px);
    float wy = py - y0f, wx = px - x0f;
    int y0 = (int)y0f, x0 = (int)x0f;
    float w00 = (1.f - wy) * (1.f - wx), w01 = (1.f - wy) * wx;
    float w10 = wy * (1.f - wx),         w11 = wy * wx;
    bool vy0 = (y0 >= 0) && (y0 < 32),  vy1 = (y0 >= -1) && (y0 < 31);
    bool vx0 = (x0 >= 0) && (x0 < 32),  vx1 = (x0 >= -1) && (x0 < 31);
    const float4* xb = (const float4*)(xs.p[b] + (size_t)(z & 3) * P_ * C_);
    int t = threadIdx.x;
    float4 a = make_float4(0.f, 0.f, 0.f, 0.f);
    if (vy0 && vx0) { float4 s = xb[(size_t)(y0 * 32 + x0) * 192 + t];
        a.x += w00 * s.x; a.y += w00 * s.y; a.z += w00 * s.z; a.w += w00 * s.w; }
    if (vy0 && vx1) { float4 s = xb[(size_t)(y0 * 32 + x0 + 1) * 192 + t];
        a.x += w01 * s.x; a.y += w01 * s.y; a.z += w01 * s.z; a.w += w01 * s.w; }
    if (vy1 && vx0) { float4 s = xb[(size_t)((y0 + 1) * 32 + x0) * 192 + t];
        a.x += w10 * s.x; a.y += w10 * s.y; a.z += w10 * s.z; a.w += w10 * s.w; }
    if (vy1 && vx1) { float4 s = xb[(size_t)((y0 + 1) * 32 + x0 + 1) * 192 + t];
        a.x += w11 * s.x; a.y += w11 * s.y; a.z += w11 * s.z; a.w += w11 * s.w; }
    a.x *= m; a.y *= m; a.z *= m; a.w *= m;
    size_t row = (size_t)z * P_ + p;
    u32* base32 = (u32*)(g_A1 + row * LDA1 + (size_t)k * 1536);
    store_split4_2seg(base32, t, a);
}

// ---------------- mma.sync fp16 GEMM -----------------------------------------
// AK=1: GEMM1, A = hi-only im2col view of g_X2 (zero-fill OOB); kc: seg=kc/12,
//       c0=(kc%12)*64; NK=108. Output MODE 0.
// AK=3: GEMM2, A = g_A1 2-slot [Ah,Al] x B=[Bh,Bh]; kc: seg=kc/24,
//       slot=(kc%24)/12, c0=(kc%12)*64; NK=216. Output MODE 1.
// AK=2: final, A = [g_blk | g_X2] 2-slot; NK=24/48. Output MODE 2.
template<int AK, int MODE>
__global__ void __launch_bounds__(THREADS, 1) gemm_mma(
    const u16* __restrict__ Bg, long ldb, int NKin, X5 xs,
    const float* __restrict__ aux, float* __restrict__ outp, Fin fin)
{
    extern __shared__ char sm[];
    u32 sbase = s2u(sm);
    const int tid = threadIdx.x;
    const int wid = tid >> 5, lane = tid & 31;
    const int wm = wid >> 2, wn = wid & 3;
    const int m0 = blockIdx.y * TM, n0 = blockIdx.x * TN;

    int NK = NKin, chN = 0, coff = 0, bsel = 0;
    const u16* Bb0 = Bg;
    if (MODE == 2) {
        bsel = blockIdx.z;
        chN = fin.chN[bsel]; coff = fin.coff[bsel]; NK = fin.nk[bsel];
        Bb0 = Bg + (size_t)bsel * 512 * ldb;
        if (n0 >= chN) return;
    }
    const char* Bbase = (const char*)(Bb0 + (size_t)n0 * ldb);
    const long ldbb = ldb * 2;
    const int arow = tid >> 2, aq = tid & 3;      // 128 rows x 4 thr, 32B each

    // A-row in the 5-block-stacked scratch buffers
    int grow = m0 + (MODE == 2 ? bsel * 4096 : 0) + arow;
    int pbase = 0, ph = 0, pw = 0;
    if (AK == 1) {
        int p = grow & 1023;
        pbase = grow - p; ph = p >> 5; pw = p & 31;
    }

    auto loadStage = [&](int s, int kc) {
        u32 sb = sbase + s * STG_BYTES;
        u32 bb = sb + 16384;
        int seg, slot, c0;
        if (AK == 1) { seg = kc / 12; slot = 0; c0 = (kc % 12) << 6; }
        else { seg = kc / 24; int rem = kc % 24; slot = rem / 12; c0 = (rem % 12) << 6; }
        // B: hi-only, slot-independent
        const char* Bgp = Bbase + (size_t)(seg * C_ + c0) * 2;
#pragma unroll
        for (int it = 0; it < 4; it++) {
            int i = it * THREADS + tid;
            int row = i >> 3, c16 = i & 7;
            u32 off = (u32)(row * 128 + c16 * 16);
            cpa16(bb + SWZ(off), Bgp + (size_t)row * ldbb + c16 * 16);
        }
        // A: 32B per thread as 2x16B
        u32 off = (u32)(arow * 128 + aq * 32);
        u32 d0 = sb + SWZ(off), d1 = sb + SWZ(off + 16);
        int elem = aq * 16;
        int soff = slot * C_ + c0 + elem;
        if (AK == 1) {
            int hh = ph + seg / 3 - 1, ww = pw + seg % 3 - 1;
            bool ok = hh >= 0 && hh < 32 && ww >= 0 && ww < 32;
            int srow = ok ? (pbase + (hh << 5) + ww) : 0;
            const u16* src = g_X2 + (size_t)srow * LDX + soff;
            u32 sz = ok ? 16u : 0u;
            cpa16z(d0, src, sz);
            cpa16z(d1, src + 8, sz);
        } else if (AK == 3) {
            const u16* src = g_A1 + (size_t)grow * LDA1 + seg * 1536 + soff;
            cpa16(d0, src);
            cpa16(d1, src + 8);
        } else {
            const u16* base = seg ? g_X2 : g_blk;
            const u16* src = base + (size_t)grow * LDX + soff;
            cpa16(d0, src);
            cpa16(d1, src + 8);
        }
        CP_COMMIT();
    };

    float acc[2][8][4];
#pragma unroll
    for (int i = 0; i < 2; i++)
#pragma unroll
        for (int j = 0; j < 8; j++)
#pragma unroll
            for (int q = 0; q < 4; q++) acc[i][j][q] = 0.f;

    loadStage(0, 0);
    loadStage(1, 1);

    for (int kc = 0; kc < NK; kc++) {
        CP_WAIT1();
        __syncthreads();
        u32 ab = sbase + (kc % 3) * STG_BYTES;
        u32 bb = ab + 16384;
#pragma unroll
        for (int ks = 0; ks < 4; ks++) {
            u32 afr[2][4];
#pragma unroll
            for (int ms = 0; ms < 2; ms++) {
                int row = wm * 32 + ms * 16 + (lane & 15);
                u32 off = (u32)(row * 128 + ks * 32 + (lane >> 4) * 16);
                LDSM4(afr[ms][0], afr[ms][1], afr[ms][2], afr[ms][3], ab + SWZ(off));
            }
#pragma unroll
            for (int np = 0; np < 4; np++) {
                int g = lane >> 3;
                int row = wn * 64 + np * 16 + ((g >> 1) & 1) * 8 + (lane & 7);
                u32 off = (u32)(row * 128 + ks * 32 + (g & 1) * 16);
                u32 bfr[4];
                LDSM4(bfr[0], bfr[1], bfr[2], bfr[3], bb + SWZ(off));
#pragma unroll
                for (int ms = 0; ms < 2; ms++) {
                    MMA16816(acc[ms][2 * np], afr[ms][0], afr[ms][1], afr[ms][2],
                             afr[ms][3], bfr[0], bfr[1]);
                    MMA16816(acc[ms][2 * np + 1], afr[ms][0], afr[ms][1], afr[ms][2],
                             afr[ms][3], bfr[2], bfr[3]);
                }
            }
        }
        __syncthreads();
        int kl = kc + 2;
        if (kl < NK) loadStage(kl % 3, kl);
        else CP_COMMIT();
    }

    // epilogue
    int quad = lane >> 2, qt = lane & 3;
#pragma unroll
    for (int ms = 0; ms < 2; ms++) {
#pragma unroll
        for (int ns = 0; ns < 8; ns++) {
            int colb = n0 + wn * 64 + ns * 8 + 2 * qt;
#pragma unroll
            for (int hh = 0; hh < 2; hh++) {
                int row = m0 + wm * 32 + ms * 16 + quad + hh * 8;
                float v0 = acc[ms][ns][2 * hh], v1 = acc[ms][ns][2 * hh + 1];
                if (MODE == 0) {
                    g_om[(size_t)row * C_ + colb]     = v0 + aux[colb];
                    g_om[(size_t)row * C_ + colb + 1] = v1 + aux[colb + 1];
                } else if (MODE == 1) {
                    float t0 = fmaxf(v0 * g_scale[colb] + g_shift[colb], 0.f);
                    float t1 = fmaxf(v1 * g_scale[colb + 1] + g_shift[colb + 1], 0.f);
                    u16 h0, l0, h1, l1;
                    split2h(t0, h0, l0); split2h(t1, h1, l1);
                    u32* p32 = (u32*)(g_blk + (size_t)row * LDX);
                    int ci = colb >> 1;
                    p32[ci]       = (u32)h0 | ((u32)h1 << 16);
                    p32[384 + ci] = (u32)l0 | ((u32)l1 << 16);
                } else {
                    // concat is along channels: plain 4096 spatial rows
                    if (colb < chN)
                        outp[(size_t)row * C_ + coff + colb] =
                            v0 + aux[(size_t)row * C_ + coff + colb];
                    if (colb + 1 < chN)
                        outp[(size_t)row * C_ + coff + colb + 1] =
                            v1 + aux[(size_t)row * C_ + coff + colb + 1];
                }
            }
        }
    }
}

// ---------------- launch -----------------------------------------------------
extern "C" void kernel_launch(void* const* d_in, const int* in_sizes, int n_in,
                              void* d_out, int out_size) {
    static u16 *pB1 = 0, *pBf = 0;
    if (!pB1) {
        cudaGetSymbolAddress((void**)&pB1, g_B1);
        cudaGetSymbolAddress((void**)&pBf, g_Bfin);
        cudaFuncSetAttribute(gemm_mma<1, 0>,
                             cudaFuncAttributeMaxDynamicSharedMemorySize, DYN_SMEM);
        cudaFuncSetAttribute(gemm_mma<3, 1>,
                             cudaFuncAttributeMaxDynamicSharedMemorySize, DYN_SMEM);
        cudaFuncSetAttribute(gemm_mma<2, 2>,
                             cudaFuncAttributeMaxDynamicSharedMemorySize, DYN_SMEM);
    }
    X5 xs;
    for (int i = 0; i < 5; i++) xs.p[i] = (const float*)d_in[i];
    const float* conv_w = (const float*)d_in[5];
    const float* conv_b = (const float*)d_in[6];
    const float* offw   = (const float*)d_in[7];
    const float* maskw  = (const float*)d_in[8];
    W10 ws;
    const int waIdx[5] = {0, 1, 2, 4, 6};
    for (int b = 0; b < 5; b++) {
        ws.a[b] = (const float*)d_in[13 + waIdx[b]];
        ws.b[b] = (b >= 2) ? (const float*)d_in[13 + waIdx[b] + 1] : ws.a[b];
    }
    float* out = (float*)d_out;
    Fin fin;
    const int CH[5]   = {30, 100, 150, 220, 268};
    const int COFF[5] = {0, 30, 130, 280, 500};
    for (int b = 0; b < 5; b++) {
        fin.chN[b] = CH[b]; fin.coff[b] = COFF[b]; fin.nk[b] = (b < 2) ? 24 : 48;
    }

    bconv_k<<<(int)(((size_t)C_ * C_ * 9 + 255) / 256), 256>>>(conv_w);
    bfin_k<<<(int)(((size_t)5 * 512 * 1536 + 255) / 256), 256>>>(ws);
    bnprep_k<<<3, 256>>>((const float*)d_in[9], (const float*)d_in[10],
                         (const float*)d_in[11], (const float*)d_in[12], conv_b);
    xsplit_k<<<dim3(4096, 5), 192>>>(xs);

    gemm_mma<1, 0><<<dim3(3, 160), THREADS, DYN_SMEM>>>(
        pB1, LDB1, 108, xs, conv_b, nullptr, fin);
    offsets_k<<<2560, 256>>>(offw, maskw);
    sample_split_k<<<dim3(P_, 9, 20), 192>>>(xs);
    gemm_mma<3, 1><<<dim3(3, 160), THREADS, DYN_SMEM>>>(
        pB1, LDB1, 216, xs, nullptr, nullptr, fin);
    gemm_mma<2, 2><<<dim3(2, 32, 5), THREADS, DYN_SMEM>>>(
        pBf, LDBF, 0, xs, xs.p[4], out, fin);
}

// round 11
// speedup vs baseline: 3.6821x; 1.4337x over previous
#include <cuda_runtime.h>
#include <cuda_fp16.h>
#include <math.h>
#include <stdint.h>

typedef unsigned short u16;
typedef uint32_t u32;
typedef uint64_t u64;

#define C_    768
#define P_    1024
#define LDA1  6912           // sampled A phys row: 9 taps x 768, hi-only fp16
#define LDX   768            // g_X2 / g_blk phys row: hi-only 768
#define LDB1  6912           // conv weight row: 9 taps x 768, hi-only
#define LDBF  1536           // 1x1 weight row: [blk 768 | x 768], hi-only
#define MBIG  20480
#define TM    128
#define TN    256
#define THREADS 512
#define STG_BYTES 49152      // A 16KB + B 32KB
#define DYN_SMEM (3 * STG_BYTES)

// ---------------- static device scratch --------------------------------------
__device__ u16  g_X2[(size_t)MBIG * LDX];          // fp16 inputs (all 5 blocks)
__device__ u16  g_blk[(size_t)MBIG * LDX];         // fp16 block outputs
__device__ u16  g_A1[(size_t)MBIG * LDA1];         // fp16 sampled A
__device__ u16  g_B1[(size_t)C_ * LDB1];           // conv weights
__device__ u16  g_Bfin[(size_t)5 * 512 * LDBF];    // 1x1 weights padded
__device__ float g_om[(size_t)MBIG * C_];
__device__ float g_off[20 * 18 * P_];
__device__ float g_mask[20 * 9 * P_];
__device__ float g_scale[C_], g_shift[C_];

struct X5  { const float* p[5]; };
struct W10 { const float* a[5]; const float* b[5]; };
struct Fin { int chN[5]; int coff[5]; int nk[5]; };

// ---------------- helpers ----------------------------------------------------
__device__ __forceinline__ u32 packh2(float a, float b) {
    return (u32)__half_as_ushort(__float2half_rn(a)) |
           ((u32)__half_as_ushort(__float2half_rn(b)) << 16);
}
__device__ __forceinline__ u32 s2u(const void* p) {
    return (u32)__cvta_generic_to_shared(p);
}
__device__ __forceinline__ void cpa16(u32 s, const void* g) {
    asm volatile("cp.async.cg.shared.global [%0], [%1], 16;"
                 :: "r"(s), "l"((u64)__cvta_generic_to_global((void*)g)));
}
__device__ __forceinline__ void cpa16z(u32 s, const void* g, u32 sz) {
    asm volatile("cp.async.cg.shared.global [%0], [%1], 16, %2;"
                 :: "r"(s), "l"((u64)__cvta_generic_to_global((void*)g)), "r"(sz));
}
#define CP_COMMIT() asm volatile("cp.async.commit_group;")
#define CP_WAIT1()  asm volatile("cp.async.wait_group 1;")
#define SWZ(o) ((o) ^ (((o) >> 3) & 0x70))
#define LDSM4(r0, r1, r2, r3, addr) \
    asm volatile("ldmatrix.sync.aligned.m8n8.x4.shared.b16 {%0,%1,%2,%3}, [%4];" \
        : "=r"(r0), "=r"(r1), "=r"(r2), "=r"(r3) : "r"(addr))
#define MMA16816(d, a0, a1, a2, a3, b0, b1) \
    asm volatile("mma.sync.aligned.m16n8k16.row.col.f32.f16.f16.f32 " \
        "{%0,%1,%2,%3}, {%4,%5,%6,%7}, {%8,%9}, {%0,%1,%2,%3};" \
        : "+f"((d)[0]), "+f"((d)[1]), "+f"((d)[2]), "+f"((d)[3]) \
        : "r"(a0), "r"(a1), "r"(a2), "r"(a3), "r"(b0), "r"(b1))

// ---------------- weight / BN prep -------------------------------------------
__global__ void bconv_k(const float* __restrict__ w) {
    size_t i = (size_t)blockIdx.x * 256 + threadIdx.x;
    if (i >= (size_t)C_ * C_ * 9) return;
    int k = (int)(i % 9);
    size_t t = i / 9;
    int c = (int)(t % C_), o = (int)(t / C_);
    g_B1[(size_t)o * LDB1 + k * C_ + c] =
        __half_as_ushort(__float2half_rn(w[i]));
}

__global__ void bfin_k(W10 ws) {
    size_t i = (size_t)blockIdx.x * 256 + threadIdx.x;
    if (i >= (size_t)5 * 512 * 1536) return;
    int cc = (int)(i % 1536);
    size_t t = i / 1536;
    int j = (int)(t % 512), b = (int)(t / 512);
    int half = cc / 768, c = cc % 768;
    const int CH[5] = {30, 100, 150, 220, 268};
    float v = 0.f;
    if (j < CH[b]) {
        if (half == 0) v = ws.a[b][j * C_ + c];
        else if (b >= 2) v = ws.b[b][j * C_ + c];
    }
    g_Bfin[((size_t)b * 512 + j) * LDBF + cc] =
        __half_as_ushort(__float2half_rn(v));
}

__global__ void bnprep_k(const float* g, const float* bt, const float* mu,
                         const float* var, const float* cb) {
    int c = blockIdx.x * 256 + threadIdx.x;
    if (c >= C_) return;
    float inv = g[c] / sqrtf(var[c] + 1e-5f);
    g_scale[c] = inv;
    g_shift[c] = cb[c] * inv + bt[c] - mu[c] * inv;
}

// ---------------- hi-only writer ---------------------------------------------
__device__ __forceinline__ void store_hi4(u32* base32, int tid, float4 v) {
    base32[2 * tid]     = packh2(v.x, v.y);
    base32[2 * tid + 1] = packh2(v.z, v.w);
}

__global__ void xsplit_k(X5 xs) {
    int row = blockIdx.x, b = blockIdx.y;
    float4 v = ((const float4*)(xs.p[b] + (size_t)row * C_))[threadIdx.x];
    u32* base32 = (u32*)(g_X2 + ((size_t)b * 4096 + row) * LDX);
    store_hi4(base32, threadIdx.x, v);
}

// ---------------- offset / mask heads ----------------------------------------
__global__ void offsets_k(const float* __restrict__ ow, const float* __restrict__ mw) {
    int lane = threadIdx.x & 31;
    int row = blockIdx.x * 8 + (threadIdx.x >> 5);
    const float* omr = g_om + (size_t)row * C_;
    float v[24];
#pragma unroll
    for (int i = 0; i < 24; i++) v[i] = omr[lane + 32 * i];
    float res[27];
#pragma unroll
    for (int o = 0; o < 27; o++) {
        const float* wr = (o < 18) ? (ow + o * C_) : (mw + (o - 18) * C_);
        float s = 0.f;
#pragma unroll
        for (int i = 0; i < 24; i++) s += v[i] * wr[lane + 32 * i];
#pragma unroll
        for (int d = 16; d; d >>= 1) s += __shfl_xor_sync(0xffffffffu, s, d);
        res[o] = s;
    }
    if (lane == 0) {
        int z = row >> 10, p = row & 1023;
#pragma unroll
        for (int o = 0; o < 18; o++) g_off[z * 18 * P_ + o * P_ + p] = res[o];
        float mx = res[18];
#pragma unroll
        for (int k = 1; k < 9; k++) mx = fmaxf(mx, res[18 + k]);
        float e[9], sum = 0.f;
#pragma unroll
        for (int k = 0; k < 9; k++) { e[k] = expf(res[18 + k] - mx); sum += e[k]; }
        float r = 1.f / sum;
#pragma unroll
        for (int k = 0; k < 9; k++) g_mask[z * 9 * P_ + p * 9 + k] = e[k] * r;
    }
}

// ---------------- deformable sampling, hi-only out ---------------------------
__global__ void sample_split_k(X5 xs) {
    int p = blockIdx.x, k = blockIdx.y, z = blockIdx.z;
    int b = z >> 2;
    float dy = g_off[z * 18 * P_ + (2 * k) * P_ + p];
    float dx = g_off[z * 18 * P_ + (2 * k + 1) * P_ + p];
    float m = g_mask[z * 9 * P_ + k * P_ + p];            // raw-reshape quirk
    int h = p >> 5, w = p & 31;
    float py = (float)(h - 1 + k / 3) + dy;
    float px = (float)(w - 1 + k % 3) + dx;
    float y0f = floorf(py), x0f = floorf(px);
    float wy = py - y0f, wx = px - x0f;
    int y0 = (int)y0f, x0 = (int)x0f;
    float w00 = (1.f - wy) * (1.f - wx), w01 = (1.f - wy) * wx;
    float w10 = wy * (1.f - wx),         w11 = wy * wx;
    bool vy0 = (y0 >= 0) && (y0 < 32),  vy1 = (y0 >= -1) && (y0 < 31);
    bool vx0 = (x0 >= 0) && (x0 < 32),  vx1 = (x0 >= -1) && (x0 < 31);
    const float4* xb = (const float4*)(xs.p[b] + (size_t)(z & 3) * P_ * C_);
    int t = threadIdx.x;
    float4 a = make_float4(0.f, 0.f, 0.f, 0.f);
    if (vy0 && vx0) { float4 s = xb[(size_t)(y0 * 32 + x0) * 192 + t];
        a.x += w00 * s.x; a.y += w00 * s.y; a.z += w00 * s.z; a.w += w00 * s.w; }
    if (vy0 && vx1) { float4 s = xb[(size_t)(y0 * 32 + x0 + 1) * 192 + t];
        a.x += w01 * s.x; a.y += w01 * s.y; a.z += w01 * s.z; a.w += w01 * s.w; }
    if (vy1 && vx0) { float4 s = xb[(size_t)((y0 + 1) * 32 + x0) * 192 + t];
        a.x += w10 * s.x; a.y += w10 * s.y; a.z += w10 * s.z; a.w += w10 * s.w; }
    if (vy1 && vx1) { float4 s = xb[(size_t)((y0 + 1) * 32 + x0 + 1) * 192 + t];
        a.x += w11 * s.x; a.y += w11 * s.y; a.z += w11 * s.z; a.w += w11 * s.w; }
    a.x *= m; a.y *= m; a.z *= m; a.w *= m;
    size_t row = (size_t)z * P_ + p;
    u32* base32 = (u32*)(g_A1 + row * LDA1 + (size_t)k * C_);
    store_hi4(base32, t, a);
}

// ---------------- mma.sync fp16 GEMM (hi-only everywhere) --------------------
// kc: seg = kc/12, c0 = (kc%12)*64
// AK=1: GEMM1, A = im2col view of g_X2 (zero-fill OOB), NK=108  -> MODE 0
// AK=3: GEMM2, A = g_A1 (seg=tap), NK=108                       -> MODE 1
// AK=2: final, A = seg?g_X2:g_blk, NK=12/24                     -> MODE 2
template<int AK, int MODE>
__global__ void __launch_bounds__(THREADS, 1) gemm_mma(
    const u16* __restrict__ Bg, long ldb, int NKin, X5 xs,
    const float* __restrict__ aux, float* __restrict__ outp, Fin fin)
{
    extern __shared__ char sm[];
    u32 sbase = s2u(sm);
    const int tid = threadIdx.x;
    const int wid = tid >> 5, lane = tid & 31;
    const int wm = wid >> 2, wn = wid & 3;
    const int m0 = blockIdx.y * TM, n0 = blockIdx.x * TN;

    int NK = NKin, chN = 0, coff = 0, bsel = 0;
    const u16* Bb0 = Bg;
    if (MODE == 2) {
        bsel = blockIdx.z;
        chN = fin.chN[bsel]; coff = fin.coff[bsel]; NK = fin.nk[bsel];
        Bb0 = Bg + (size_t)bsel * 512 * ldb;
        if (n0 >= chN) return;
    }
    const char* Bbase = (const char*)(Bb0 + (size_t)n0 * ldb);
    const long ldbb = ldb * 2;
    const int arow = tid >> 2, aq = tid & 3;      // 128 rows x 4 thr, 32B each

    // A-row in the 5-block-stacked scratch buffers
    int grow = m0 + (MODE == 2 ? bsel * 4096 : 0) + arow;
    int pbase = 0, ph = 0, pw = 0;
    if (AK == 1) {
        int p = grow & 1023;
        pbase = grow - p; ph = p >> 5; pw = p & 31;
    }

    auto loadStage = [&](int s, int kc) {
        u32 sb = sbase + s * STG_BYTES;
        u32 bb = sb + 16384;
        int seg = kc / 12, c0 = (kc % 12) << 6;
        const char* Bgp = Bbase + (size_t)(seg * C_ + c0) * 2;
#pragma unroll
        for (int it = 0; it < 4; it++) {
            int i = it * THREADS + tid;
            int row = i >> 3, c16 = i & 7;
            u32 off = (u32)(row * 128 + c16 * 16);
            cpa16(bb + SWZ(off), Bgp + (size_t)row * ldbb + c16 * 16);
        }
        // A: 32B per thread as 2x16B
        u32 off = (u32)(arow * 128 + aq * 32);
        u32 d0 = sb + SWZ(off), d1 = sb + SWZ(off + 16);
        int elem = c0 + aq * 16;
        if (AK == 1) {
            int hh = ph + seg / 3 - 1, ww = pw + seg % 3 - 1;
            bool ok = hh >= 0 && hh < 32 && ww >= 0 && ww < 32;
            int srow = ok ? (pbase + (hh << 5) + ww) : 0;
            const u16* src = g_X2 + (size_t)srow * LDX + elem;
            u32 sz = ok ? 16u : 0u;
            cpa16z(d0, src, sz);
            cpa16z(d1, src + 8, sz);
        } else if (AK == 3) {
            const u16* src = g_A1 + (size_t)grow * LDA1 + seg * C_ + elem;
            cpa16(d0, src);
            cpa16(d1, src + 8);
        } else {
            const u16* base = seg ? g_X2 : g_blk;
            const u16* src = base + (size_t)grow * LDX + elem;
            cpa16(d0, src);
            cpa16(d1, src + 8);
        }
        CP_COMMIT();
    };

    float acc[2][8][4];
#pragma unroll
    for (int i = 0; i < 2; i++)
#pragma unroll
        for (int j = 0; j < 8; j++)
#pragma unroll
            for (int q = 0; q < 4; q++) acc[i][j][q] = 0.f;

    loadStage(0, 0);
    loadStage(1, 1);

    for (int kc = 0; kc < NK; kc++) {
        CP_WAIT1();
        __syncthreads();
        u32 ab = sbase + (kc % 3) * STG_BYTES;
        u32 bb = ab + 16384;
#pragma unroll
        for (int ks = 0; ks < 4; ks++) {
            u32 afr[2][4];
#pragma unroll
            for (int ms = 0; ms < 2; ms++) {
                int row = wm * 32 + ms * 16 + (lane & 15);
                u32 off = (u32)(row * 128 + ks * 32 + (lane >> 4) * 16);
                LDSM4(afr[ms][0], afr[ms][1], afr[ms][2], afr[ms][3], ab + SWZ(off));
            }
#pragma unroll
            for (int np = 0; np < 4; np++) {
                int g = lane >> 3;
                int row = wn * 64 + np * 16 + ((g >> 1) & 1) * 8 + (lane & 7);
                u32 off = (u32)(row * 128 + ks * 32 + (g & 1) * 16);
                u32 bfr[4];
                LDSM4(bfr[0], bfr[1], bfr[2], bfr[3], bb + SWZ(off));
#pragma unroll
                for (int ms = 0; ms < 2; ms++) {
                    MMA16816(acc[ms][2 * np], afr[ms][0], afr[ms][1], afr[ms][2],
                             afr[ms][3], bfr[0], bfr[1]);
                    MMA16816(acc[ms][2 * np + 1], afr[ms][0], afr[ms][1], afr[ms][2],
                             afr[ms][3], bfr[2], bfr[3]);
                }
            }
        }
        __syncthreads();
        int kl = kc + 2;
        if (kl < NK) loadStage(kl % 3, kl);
        else CP_COMMIT();
    }

    // epilogue
    int quad = lane >> 2, qt = lane & 3;
#pragma unroll
    for (int ms = 0; ms < 2; ms++) {
#pragma unroll
        for (int ns = 0; ns < 8; ns++) {
            int colb = n0 + wn * 64 + ns * 8 + 2 * qt;
#pragma unroll
            for (int hh = 0; hh < 2; hh++) {
                int row = m0 + wm * 32 + ms * 16 + quad + hh * 8;
                float v0 = acc[ms][ns][2 * hh], v1 = acc[ms][ns][2 * hh + 1];
                if (MODE == 0) {
                    g_om[(size_t)row * C_ + colb]     = v0 + aux[colb];
                    g_om[(size_t)row * C_ + colb + 1] = v1 + aux[colb + 1];
                } else if (MODE == 1) {
                    float t0 = fmaxf(v0 * g_scale[colb] + g_shift[colb], 0.f);
                    float t1 = fmaxf(v1 * g_scale[colb + 1] + g_shift[colb + 1], 0.f);
                    ((u32*)(g_blk + (size_t)row * LDX))[colb >> 1] = packh2(t0, t1);
                } else {
                    // concat is along channels: plain 4096 spatial rows
                    if (colb < chN)
                        outp[(size_t)row * C_ + coff + colb] =
                            v0 + aux[(size_t)row * C_ + coff + colb];
                    if (colb + 1 < chN)
                        outp[(size_t)row * C_ + coff + colb + 1] =
                            v1 + aux[(size_t)row * C_ + coff + colb + 1];
                }
            }
        }
    }
}

// ---------------- launch -----------------------------------------------------
extern "C" void kernel_launch(void* const* d_in, const int* in_sizes, int n_in,
                              void* d_out, int out_size) {
    static u16 *pB1 = 0, *pBf = 0;
    if (!pB1) {
        cudaGetSymbolAddress((void**)&pB1, g_B1);
        cudaGetSymbolAddress((void**)&pBf, g_Bfin);
        cudaFuncSetAttribute(gemm_mma<1, 0>,
                             cudaFuncAttributeMaxDynamicSharedMemorySize, DYN_SMEM);
        cudaFuncSetAttribute(gemm_mma<3, 1>,
                             cudaFuncAttributeMaxDynamicSharedMemorySize, DYN_SMEM);
        cudaFuncSetAttribute(gemm_mma<2, 2>,
                             cudaFuncAttributeMaxDynamicSharedMemorySize, DYN_SMEM);
    }
    X5 xs;
    for (int i = 0; i < 5; i++) xs.p[i] = (const float*)d_in[i];
    const float* conv_w = (const float*)d_in[5];
    const float* conv_b = (const float*)d_in[6];
    const float* offw   = (const float*)d_in[7];
    const float* maskw  = (const float*)d_in[8];
    W10 ws;
    const int waIdx[5] = {0, 1, 2, 4, 6};
    for (int b = 0; b < 5; b++) {
        ws.a[b] = (const float*)d_in[13 + waIdx[b]];
        ws.b[b] = (b >= 2) ? (const float*)d_in[13 + waIdx[b] + 1] : ws.a[b];
    }
    float* out = (float*)d_out;
    Fin fin;
    const int CH[5]   = {30, 100, 150, 220, 268};
    const int COFF[5] = {0, 30, 130, 280, 500};
    for (int b = 0; b < 5; b++) {
        fin.chN[b] = CH[b]; fin.coff[b] = COFF[b]; fin.nk[b] = (b < 2) ? 12 : 24;
    }

    bconv_k<<<(int)(((size_t)C_ * C_ * 9 + 255) / 256), 256>>>(conv_w);
    bfin_k<<<(int)(((size_t)5 * 512 * 1536 + 255) / 256), 256>>>(ws);
    bnprep_k<<<3, 256>>>((const float*)d_in[9], (const float*)d_in[10],
                         (const float*)d_in[11], (const float*)d_in[12], conv_b);
    xsplit_k<<<dim3(4096, 5), 192>>>(xs);

    gemm_mma<1, 0><<<dim3(3, 160), THREADS, DYN_SMEM>>>(
        pB1, LDB1, 108, xs, conv_b, nullptr, fin);
    offsets_k<<<2560, 256>>>(offw, maskw);
    sample_split_k<<<dim3(P_, 9, 20), 192>>>(xs);
    gemm_mma<3, 1><<<dim3(3, 160), THREADS, DYN_SMEM>>>(
        pB1, LDB1, 108, xs, nullptr, nullptr, fin);
    gemm_mma<2, 2><<<dim3(2, 32, 5), THREADS, DYN_SMEM>>>(
        pBf, LDBF, 0, xs, xs.p[4], out, fin);
}

// round 12
// speedup vs baseline: 5.2666x; 1.4303x over previous
#include <cuda_runtime.h>
#include <cuda_fp16.h>
#include <math.h>
#include <stdint.h>

typedef unsigned short u16;
typedef uint32_t u32;
typedef uint64_t u64;

#define C_    768
#define P_    1024
#define LDA1  6912           // sampled A phys row: 9 taps x 768, hi-only fp16
#define LDX   768            // g_X2 / g_blk phys row: hi-only 768
#define LDB1  6912           // conv weight row: 9 taps x 768
#define LDBF  1536           // 1x1 weight row: [blk 768 | x 768]
#define MBIG  20480
#define TM    128
#define TN    256
#define THREADS 512
#define STG_BYTES 49152      // A 16KB + B 32KB
#define DYN_SMEM (3 * STG_BYTES)
#define STG_OFF 20480        // A 16KB + B 4KB
#define DYN_OFF (3 * STG_OFF)

// ---------------- static device scratch --------------------------------------
__device__ u16  g_X2[(size_t)MBIG * LDX];          // fp16 inputs (all 5 blocks)
__device__ u16  g_blk[(size_t)MBIG * LDX];         // fp16 block outputs
__device__ u16  g_A1[(size_t)MBIG * LDA1];         // fp16 sampled A
__device__ u16  g_B1[(size_t)C_ * LDB1];           // conv weights
__device__ u16  g_Bfin[(size_t)5 * 512 * LDBF];    // 1x1 weights padded
__device__ u16  g_Weff[(size_t)32 * LDB1];         // composed head weights fp16
__device__ float g_be[32];                         // composed head bias
__device__ float g_omx[(size_t)MBIG * 32];         // raw head outputs
__device__ float g_off[20 * 18 * P_];
__device__ float g_mask[20 * 9 * P_];
__device__ float g_scale[C_], g_shift[C_];

struct X5  { const float* p[5]; };
struct W10 { const float* a[5]; const float* b[5]; };
struct Fin { int chN[5]; int coff[5]; int nk[5]; };

// ---------------- helpers ----------------------------------------------------
__device__ __forceinline__ u32 packh2(float a, float b) {
    return (u32)__half_as_ushort(__float2half_rn(a)) |
           ((u32)__half_as_ushort(__float2half_rn(b)) << 16);
}
__device__ __forceinline__ u32 s2u(const void* p) {
    return (u32)__cvta_generic_to_shared(p);
}
__device__ __forceinline__ void cpa16(u32 s, const void* g) {
    asm volatile("cp.async.cg.shared.global [%0], [%1], 16;"
                 :: "r"(s), "l"((u64)__cvta_generic_to_global((void*)g)));
}
__device__ __forceinline__ void cpa16z(u32 s, const void* g, u32 sz) {
    asm volatile("cp.async.cg.shared.global [%0], [%1], 16, %2;"
                 :: "r"(s), "l"((u64)__cvta_generic_to_global((void*)g)), "r"(sz));
}
#define CP_COMMIT() asm volatile("cp.async.commit_group;")
#define CP_WAIT1()  asm volatile("cp.async.wait_group 1;")
#define SWZ(o) ((o) ^ (((o) >> 3) & 0x70))
#define LDSM4(r0, r1, r2, r3, addr) \
    asm volatile("ldmatrix.sync.aligned.m8n8.x4.shared.b16 {%0,%1,%2,%3}, [%4];" \
        : "=r"(r0), "=r"(r1), "=r"(r2), "=r"(r3) : "r"(addr))
#define MMA16816(d, a0, a1, a2, a3, b0, b1) \
    asm volatile("mma.sync.aligned.m16n8k16.row.col.f32.f16.f16.f32 " \
        "{%0,%1,%2,%3}, {%4,%5,%6,%7}, {%8,%9}, {%0,%1,%2,%3};" \
        : "+f"((d)[0]), "+f"((d)[1]), "+f"((d)[2]), "+f"((d)[3]) \
        : "r"(a0), "r"(a1), "r"(a2), "r"(a3), "r"(b0), "r"(b1))

// ---------------- weight / BN prep -------------------------------------------
__global__ void bconv_k(const float* __restrict__ w) {
    size_t i = (size_t)blockIdx.x * 256 + threadIdx.x;
    if (i >= (size_t)C_ * C_ * 9) return;
    int k = (int)(i % 9);
    size_t t = i / 9;
    int c = (int)(t % C_), o = (int)(t / C_);
    g_B1[(size_t)o * LDB1 + k * C_ + c] =
        __half_as_ushort(__float2half_rn(w[i]));
}

__global__ void bfin_k(W10 ws) {
    size_t i = (size_t)blockIdx.x * 256 + threadIdx.x;
    if (i >= (size_t)5 * 512 * 1536) return;
    int cc = (int)(i % 1536);
    size_t t = i / 1536;
    int j = (int)(t % 512), b = (int)(t / 512);
    int half = cc / 768, c = cc % 768;
    const int CH[5] = {30, 100, 150, 220, 268};
    float v = 0.f;
    if (j < CH[b]) {
        if (half == 0) v = ws.a[b][j * C_ + c];
        else if (b >= 2) v = ws.b[b][j * C_ + c];
    }
    g_Bfin[((size_t)b * 512 + j) * LDBF + cc] =
        __half_as_ushort(__float2half_rn(v));
}

__global__ void bnprep_k(const float* g, const float* bt, const float* mu,
                         const float* var, const float* cb) {
    int c = blockIdx.x * 256 + threadIdx.x;
    if (c >= C_) return;
    float inv = g[c] / sqrtf(var[c] + 1e-5f);
    g_scale[c] = inv;
    g_shift[c] = cb[c] * inv + bt[c] - mu[c] * inv;
}

// Weff[o][k*768+cin] = sum_c head_w[o][c] * conv_w[c][cin][k]   (fp32 compose)
__global__ void weff_k(const float* __restrict__ cw,
                       const float* __restrict__ ow, const float* __restrict__ mw) {
    __shared__ float sow[32][33];
    int k = blockIdx.x / 12, cin0 = (blockIdx.x % 12) * 64;
    int tid = threadIdx.x;
    int cin = tid & 63, og = tid >> 6;          // og 0..3 -> o = og*8+j
    float acc[8];
#pragma unroll
    for (int j = 0; j < 8; j++) acc[j] = 0.f;
    for (int cc0 = 0; cc0 < 768; cc0 += 32) {
#pragma unroll
        for (int it = 0; it < 4; it++) {
            int i = it * 256 + tid;
            int c = i >> 5, o = i & 31;
            float v = 0.f;
            if (o < 18)      v = ow[o * 768 + cc0 + c];
            else if (o < 27) v = mw[(o - 18) * 768 + cc0 + c];
            sow[c][o] = v;
        }
        __syncthreads();
#pragma unroll 4
        for (int c = 0; c < 32; c++) {
            float cwv = cw[((size_t)(cc0 + c) * 768 + cin0 + cin) * 9 + k];
#pragma unroll
            for (int j = 0; j < 8; j++) acc[j] += cwv * sow[c][og * 8 + j];
        }
        __syncthreads();
    }
#pragma unroll
    for (int j = 0; j < 8; j++) {
        int o = og * 8 + j;
        g_Weff[(size_t)o * LDB1 + k * 768 + cin0 + cin] =
            __half_as_ushort(__float2half_rn(acc[j]));
    }
}

__global__ void beprep_k(const float* __restrict__ ow, const float* __restrict__ mw,
                         const float* __restrict__ cb) {
    int tid = threadIdx.x;                       // 256
    int o = tid >> 3, l8 = tid & 7;
    float s = 0.f;
    if (o < 27) {
        const float* wr = (o < 18) ? (ow + o * 768) : (mw + (o - 18) * 768);
        for (int c = l8; c < 768; c += 8) s += wr[c] * cb[c];
    }
#pragma unroll
    for (int d = 4; d; d >>= 1) s += __shfl_xor_sync(0xffffffffu, s, d);
    if (l8 == 0) g_be[o] = (o < 27) ? s : 0.f;
}

// ---------------- hi-only writer ---------------------------------------------
__device__ __forceinline__ void store_hi4(u32* base32, int tid, float4 v) {
    base32[2 * tid]     = packh2(v.x, v.y);
    base32[2 * tid + 1] = packh2(v.z, v.w);
}

__global__ void xsplit_k(X5 xs) {
    int row = blockIdx.x, b = blockIdx.y;
    float4 v = ((const float4*)(xs.p[b] + (size_t)row * C_))[threadIdx.x];
    u32* base32 = (u32*)(g_X2 + ((size_t)b * 4096 + row) * LDX);
    store_hi4(base32, threadIdx.x, v);
}

// ---------------- narrow head GEMM: g_omx = im2col(g_X2) @ Weff^T + be -------
__global__ void __launch_bounds__(256, 1) gemm_off() {
    extern __shared__ char sm[];
    u32 sbase = s2u(sm);
    const int tid = threadIdx.x;
    const int wid = tid >> 5, lane = tid & 31;
    const int m0 = blockIdx.x * TM;

    auto loadStage = [&](int s, int kc) {
        u32 sb = sbase + s * STG_OFF;
        u32 bbs = sb + 16384;
        int seg = kc / 12, c0 = (kc % 12) << 6;
        {
            int row = tid >> 3, c16 = tid & 7;
            u32 off = (u32)(row * 128 + c16 * 16);
            cpa16(bbs + SWZ(off),
                  g_Weff + (size_t)row * LDB1 + seg * 768 + c0 + c16 * 8);
        }
        int ky = seg / 3 - 1, kx = seg % 3 - 1;
#pragma unroll
        for (int it = 0; it < 4; it++) {
            int i = it * 256 + tid;
            int row = i >> 3, c16 = i & 7;
            int grow = m0 + row;
            int p = grow & 1023;
            int hh = (p >> 5) + ky, ww = (p & 31) + kx;
            bool ok = hh >= 0 && hh < 32 && ww >= 0 && ww < 32;
            int srow = ok ? (grow - p + (hh << 5) + ww) : 0;
            u32 off = (u32)(row * 128 + c16 * 16);
            cpa16z(sb + SWZ(off), g_X2 + (size_t)srow * LDX + c0 + c16 * 8,
                   ok ? 16u : 0u);
        }
        CP_COMMIT();
    };

    float acc[4][4];
#pragma unroll
    for (int i = 0; i < 4; i++)
#pragma unroll
        for (int q = 0; q < 4; q++) acc[i][q] = 0.f;

    loadStage(0, 0);
    loadStage(1, 1);

    for (int kc = 0; kc < 108; kc++) {
        CP_WAIT1();
        __syncthreads();
        u32 ab = sbase + (kc % 3) * STG_OFF;
        u32 bb = ab + 16384;
#pragma unroll
        for (int ks = 0; ks < 4; ks++) {
            u32 afr[4];
            int arw = wid * 16 + (lane & 15);
            u32 aoff = (u32)(arw * 128 + ks * 32 + (lane >> 4) * 16);
            LDSM4(afr[0], afr[1], afr[2], afr[3], ab + SWZ(aoff));
#pragma unroll
            for (int np2 = 0; np2 < 2; np2++) {
                int g = lane >> 3;
                int brow = np2 * 16 + ((g >> 1) & 1) * 8 + (lane & 7);
                u32 boff = (u32)(brow * 128 + ks * 32 + (g & 1) * 16);
                u32 bfr[4];
                LDSM4(bfr[0], bfr[1], bfr[2], bfr[3], bb + SWZ(boff));
                MMA16816(acc[2 * np2], afr[0], afr[1], afr[2], afr[3],
                         bfr[0], bfr[1]);
                MMA16816(acc[2 * np2 + 1], afr[0], afr[1], afr[2], afr[3],
                         bfr[2], bfr[3]);
            }
        }
        __syncthreads();
        int kl = kc + 2;
        if (kl < 108) loadStage(kl % 3, kl);
        else CP_COMMIT();
    }

    int quad = lane >> 2, qt = lane & 3;
#pragma unroll
    for (int np = 0; np < 4; np++) {
        int colb = np * 8 + 2 * qt;
#pragma unroll
        for (int hh = 0; hh < 2; hh++) {
            int row = m0 + wid * 16 + quad + hh * 8;
            g_omx[(size_t)row * 32 + colb]     = acc[np][2 * hh]     + g_be[colb];
            g_omx[(size_t)row * 32 + colb + 1] = acc[np][2 * hh + 1] + g_be[colb + 1];
        }
    }
}

// ---------------- per-row offsets + softmax ----------------------------------
__global__ void offlite_k() {
    int row = blockIdx.x * 256 + threadIdx.x;   // 0..20479
    int z = row >> 10, p = row & 1023;
    const float* src = g_omx + (size_t)row * 32;
    float res[27];
#pragma unroll
    for (int o = 0; o < 27; o++) res[o] = src[o];
#pragma unroll
    for (int o = 0; o < 18; o++) g_off[z * 18 * P_ + o * P_ + p] = res[o];
    float mx = res[18];
#pragma unroll
    for (int k = 1; k < 9; k++) mx = fmaxf(mx, res[18 + k]);
    float e[9], sum = 0.f;
#pragma unroll
    for (int k = 0; k < 9; k++) { e[k] = expf(res[18 + k] - mx); sum += e[k]; }
    float r = 1.f / sum;
#pragma unroll
    for (int k = 0; k < 9; k++) g_mask[z * 9 * P_ + p * 9 + k] = e[k] * r;
}

// ---------------- deformable sampling, hi-only out ---------------------------
__global__ void sample_split_k(X5 xs) {
    int p = blockIdx.x, k = blockIdx.y, z = blockIdx.z;
    int b = z >> 2;
    float dy = g_off[z * 18 * P_ + (2 * k) * P_ + p];
    float dx = g_off[z * 18 * P_ + (2 * k + 1) * P_ + p];
    float m = g_mask[z * 9 * P_ + k * P_ + p];            // raw-reshape quirk
    int h = p >> 5, w = p & 31;
    float py = (float)(h - 1 + k / 3) + dy;
    float px = (float)(w - 1 + k % 3) + dx;
    float y0f = floorf(py), x0f = floorf(px);
    float wy = py - y0f, wx = px - x0f;
    int y0 = (int)y0f, x0 = (int)x0f;
    float w00 = (1.f - wy) * (1.f - wx), w01 = (1.f - wy) * wx;
    float w10 = wy * (1.f - wx),         w11 = wy * wx;
    bool vy0 = (y0 >= 0) && (y0 < 32),  vy1 = (y0 >= -1) && (y0 < 31);
    bool vx0 = (x0 >= 0) && (x0 < 32),  vx1 = (x0 >= -1) && (x0 < 31);
    const float4* xb = (const float4*)(xs.p[b] + (size_t)(z & 3) * P_ * C_);
    int t = threadIdx.x;
    float4 a = make_float4(0.f, 0.f, 0.f, 0.f);
    if (vy0 && vx0) { float4 s = xb[(size_t)(y0 * 32 + x0) * 192 + t];
        a.x += w00 * s.x; a.y += w00 * s.y; a.z += w00 * s.z; a.w += w00 * s.w; }
    if (vy0 && vx1) { float4 s = xb[(size_t)(y0 * 32 + x0 + 1) * 192 + t];
        a.x += w01 * s.x; a.y += w01 * s.y; a.z += w01 * s.z; a.w += w01 * s.w; }
    if (vy1 && vx0) { float4 s = xb[(size_t)((y0 + 1) * 32 + x0) * 192 + t];
        a.x += w10 * s.x; a.y += w10 * s.y; a.z += w10 * s.z; a.w += w10 * s.w; }
    if (vy1 && vx1) { float4 s = xb[(size_t)((y0 + 1) * 32 + x0 + 1) * 192 + t];
        a.x += w11 * s.x; a.y += w11 * s.y; a.z += w11 * s.z; a.w += w11 * s.w; }
    a.x *= m; a.y *= m; a.z *= m; a.w *= m;
    size_t row = (size_t)z * P_ + p;
    u32* base32 = (u32*)(g_A1 + row * LDA1 + (size_t)k * C_);
    store_hi4(base32, t, a);
}

// ---------------- mma.sync fp16 GEMM -----------------------------------------
// kc: seg = kc/12, c0 = (kc%12)*64
// AK=3: GEMM2, A = g_A1 (seg=tap), NK=108          -> MODE 1
// AK=2: final, A = seg?g_X2:g_blk, NK=12/24        -> MODE 2
template<int AK, int MODE>
__global__ void __launch_bounds__(THREADS, 1) gemm_mma(
    const u16* __restrict__ Bg, long ldb, int NKin, X5 xs,
    const float* __restrict__ aux, float* __restrict__ outp, Fin fin)
{
    extern __shared__ char sm[];
    u32 sbase = s2u(sm);
    const int tid = threadIdx.x;
    const int wid = tid >> 5, lane = tid & 31;
    const int wm = wid >> 2, wn = wid & 3;
    const int m0 = blockIdx.y * TM, n0 = blockIdx.x * TN;

    int NK = NKin, chN = 0, coff = 0, bsel = 0;
    const u16* Bb0 = Bg;
    if (MODE == 2) {
        bsel = blockIdx.z;
        chN = fin.chN[bsel]; coff = fin.coff[bsel]; NK = fin.nk[bsel];
        Bb0 = Bg + (size_t)bsel * 512 * ldb;
        if (n0 >= chN) return;
    }
    const char* Bbase = (const char*)(Bb0 + (size_t)n0 * ldb);
    const long ldbb = ldb * 2;
    const int arow = tid >> 2, aq = tid & 3;      // 128 rows x 4 thr, 32B each
    int grow = m0 + (MODE == 2 ? bsel * 4096 : 0) + arow;

    auto loadStage = [&](int s, int kc) {
        u32 sb = sbase + s * STG_BYTES;
        u32 bb = sb + 16384;
        int seg = kc / 12, c0 = (kc % 12) << 6;
        const char* Bgp = Bbase + (size_t)(seg * C_ + c0) * 2;
#pragma unroll
        for (int it = 0; it < 4; it++) {
            int i = it * THREADS + tid;
            int row = i >> 3, c16 = i & 7;
            u32 off = (u32)(row * 128 + c16 * 16);
            cpa16(bb + SWZ(off), Bgp + (size_t)row * ldbb + c16 * 16);
        }
        u32 off = (u32)(arow * 128 + aq * 32);
        u32 d0 = sb + SWZ(off), d1 = sb + SWZ(off + 16);
        int elem = c0 + aq * 16;
        if (AK == 3) {
            const u16* src = g_A1 + (size_t)grow * LDA1 + seg * C_ + elem;
            cpa16(d0, src);
            cpa16(d1, src + 8);
        } else {
            const u16* base = seg ? g_X2 : g_blk;
            const u16* src = base + (size_t)grow * LDX + elem;
            cpa16(d0, src);
            cpa16(d1, src + 8);
        }
        CP_COMMIT();
    };

    float acc[2][8][4];
#pragma unroll
    for (int i = 0; i < 2; i++)
#pragma unroll
        for (int j = 0; j < 8; j++)
#pragma unroll
            for (int q = 0; q < 4; q++) acc[i][j][q] = 0.f;

    loadStage(0, 0);
    loadStage(1, 1);

    for (int kc = 0; kc < NK; kc++) {
        CP_WAIT1();
        __syncthreads();
        u32 ab = sbase + (kc % 3) * STG_BYTES;
        u32 bb = ab + 16384;
#pragma unroll
        for (int ks = 0; ks < 4; ks++) {
            u32 afr[2][4];
#pragma unroll
            for (int ms = 0; ms < 2; ms++) {
                int row = wm * 32 + ms * 16 + (lane & 15);
                u32 off = (u32)(row * 128 + ks * 32 + (lane >> 4) * 16);
                LDSM4(afr[ms][0], afr[ms][1], afr[ms][2], afr[ms][3], ab + SWZ(off));
            }
#pragma unroll
            for (int np = 0; np < 4; np++) {
                int g = lane >> 3;
                int row = wn * 64 + np * 16 + ((g >> 1) & 1) * 8 + (lane & 7);
                u32 off = (u32)(row * 128 + ks * 32 + (g & 1) * 16);
                u32 bfr[4];
                LDSM4(bfr[0], bfr[1], bfr[2], bfr[3], bb + SWZ(off));
#pragma unroll
                for (int ms = 0; ms < 2; ms++) {
                    MMA16816(acc[ms][2 * np], afr[ms][0], afr[ms][1], afr[ms][2],
                             afr[ms][3], bfr[0], bfr[1]);
                    MMA16816(acc[ms][2 * np + 1], afr[ms][0], afr[ms][1], afr[ms][2],
                             afr[ms][3], bfr[2], bfr[3]);
                }
            }
        }
        __syncthreads();
        int kl = kc + 2;
        if (kl < NK) loadStage(kl % 3, kl);
        else CP_COMMIT();
    }

    // epilogue
    int quad = lane >> 2, qt = lane & 3;
#pragma unroll
    for (int ms = 0; ms < 2; ms++) {
#pragma unroll
        for (int ns = 0; ns < 8; ns++) {
            int colb = n0 + wn * 64 + ns * 8 + 2 * qt;
#pragma unroll
            for (int hh = 0; hh < 2; hh++) {
                int row = m0 + wm * 32 + ms * 16 + quad + hh * 8;
                float v0 = acc[ms][ns][2 * hh], v1 = acc[ms][ns][2 * hh + 1];
                if (MODE == 1) {
                    float t0 = fmaxf(v0 * g_scale[colb] + g_shift[colb], 0.f);
                    float t1 = fmaxf(v1 * g_scale[colb + 1] + g_shift[colb + 1], 0.f);
                    ((u32*)(g_blk + (size_t)row * LDX))[colb >> 1] = packh2(t0, t1);
                } else {
                    // concat is along channels: plain 4096 spatial rows
                    if (colb < chN)
                        outp[(size_t)row * C_ + coff + colb] =
                            v0 + aux[(size_t)row * C_ + coff + colb];
                    if (colb + 1 < chN)
                        outp[(size_t)row * C_ + coff + colb + 1] =
                            v1 + aux[(size_t)row * C_ + coff + colb + 1];
                }
            }
        }
    }
}

// ---------------- launch -----------------------------------------------------
extern "C" void kernel_launch(void* const* d_in, const int* in_sizes, int n_in,
                              void* d_out, int out_size) {
    static u16 *pB1 = 0, *pBf = 0;
    if (!pB1) {
        cudaGetSymbolAddress((void**)&pB1, g_B1);
        cudaGetSymbolAddress((void**)&pBf, g_Bfin);
        cudaFuncSetAttribute(gemm_mma<3, 1>,
                             cudaFuncAttributeMaxDynamicSharedMemorySize, DYN_SMEM);
        cudaFuncSetAttribute(gemm_mma<2, 2>,
                             cudaFuncAttributeMaxDynamicSharedMemorySize, DYN_SMEM);
        cudaFuncSetAttribute(gemm_off,
                             cudaFuncAttributeMaxDynamicSharedMemorySize, DYN_OFF);
    }
    X5 xs;
    for (int i = 0; i < 5; i++) xs.p[i] = (const float*)d_in[i];
    const float* conv_w = (const float*)d_in[5];
    const float* conv_b = (const float*)d_in[6];
    const float* offw   = (const float*)d_in[7];
    const float* maskw  = (const float*)d_in[8];
    W10 ws;
    const int waIdx[5] = {0, 1, 2, 4, 6};
    for (int b = 0; b < 5; b++) {
        ws.a[b] = (const float*)d_in[13 + waIdx[b]];
        ws.b[b] = (b >= 2) ? (const float*)d_in[13 + waIdx[b] + 1] : ws.a[b];
    }
    float* out = (float*)d_out;
    Fin fin;
    const int CH[5]   = {30, 100, 150, 220, 268};
    const int COFF[5] = {0, 30, 130, 280, 500};
    for (int b = 0; b < 5; b++) {
        fin.chN[b] = CH[b]; fin.coff[b] = COFF[b]; fin.nk[b] = (b < 2) ? 12 : 24;
    }

    bconv_k<<<(int)(((size_t)C_ * C_ * 9 + 255) / 256), 256>>>(conv_w);
    bfin_k<<<(int)(((size_t)5 * 512 * 1536 + 255) / 256), 256>>>(ws);
    bnprep_k<<<3, 256>>>((const float*)d_in[9], (const float*)d_in[10],
                         (const float*)d_in[11], (const float*)d_in[12], conv_b);
    weff_k<<<108, 256>>>(conv_w, offw, maskw);
    beprep_k<<<1, 256>>>(offw, maskw, conv_b);
    xsplit_k<<<dim3(4096, 5), 192>>>(xs);

    gemm_off<<<160, 256, DYN_OFF>>>();
    offlite_k<<<80, 256>>>();
    sample_split_k<<<dim3(P_, 9, 20), 192>>>(xs);
    gemm_mma<3, 1><<<dim3(3, 160), THREADS, DYN_SMEM>>>(
        pB1, LDB1, 108, xs, nullptr, nullptr, fin);
    gemm_mma<2, 2><<<dim3(2, 32, 5), THREADS, DYN_SMEM>>>(
        pBf, LDBF, 0, xs, xs.p[4], out, fin);
}

// round 13
// speedup vs baseline: 5.9163x; 1.1234x over previous
#include <cuda_runtime.h>
#include <cuda_fp16.h>
#include <math.h>
#include <stdint.h>

typedef unsigned short u16;
typedef uint32_t u32;
typedef uint64_t u64;

#define C_    768
#define P_    1024
#define LDA1  6912           // sampled A phys row: 9 taps x 768, hi-only fp16
#define LDX   768            // g_X2 / g_blk phys row: hi-only 768
#define LDB1  6912           // conv weight row: 9 taps x 768
#define LDBF  1536           // 1x1 weight row: [blk 768 | x 768]
#define MBIG  20480
#define TM    128
#define TN    256
#define THREADS 512
#define STG_BYTES 49152      // A 16KB + B 32KB
#define DYN_SMEM (3 * STG_BYTES)
#define STG_OFF 20480        // A 16KB + B 4KB
#define DYN_OFF (3 * STG_OFF)
#define DYN_WEFF (768 * 28 * 4)   // 86016 B

// ---------------- static device scratch --------------------------------------
__device__ u16  g_X2[(size_t)MBIG * LDX];          // fp16 inputs (all 5 blocks)
__device__ u16  g_blk[(size_t)MBIG * LDX];         // fp16 block outputs
__device__ u16  g_A1[(size_t)MBIG * LDA1];         // fp16 sampled A
__device__ u16  g_B1[(size_t)C_ * LDB1];           // conv weights
__device__ u16  g_Bfin[(size_t)5 * 512 * LDBF];    // 1x1 weights padded
__device__ u16  g_Weff[(size_t)32 * LDB1];         // composed head weights fp16
__device__ float g_be[32];                         // composed head bias
__device__ float g_omx[(size_t)MBIG * 32];         // raw head outputs
__device__ float g_off[20 * 18 * P_];
__device__ float g_mask[20 * 9 * P_];
__device__ float g_scale[C_], g_shift[C_];

struct X5  { const float* p[5]; };
struct W10 { const float* a[5]; const float* b[5]; };
struct Fin { int chN[5]; int coff[5]; int nk[5]; };

// ---------------- helpers ----------------------------------------------------
__device__ __forceinline__ u32 packh2(float a, float b) {
    return (u32)__half_as_ushort(__float2half_rn(a)) |
           ((u32)__half_as_ushort(__float2half_rn(b)) << 16);
}
__device__ __forceinline__ u32 s2u(const void* p) {
    return (u32)__cvta_generic_to_shared(p);
}
__device__ __forceinline__ void cpa16(u32 s, const void* g) {
    asm volatile("cp.async.cg.shared.global [%0], [%1], 16;"
                 :: "r"(s), "l"((u64)__cvta_generic_to_global((void*)g)));
}
__device__ __forceinline__ void cpa16z(u32 s, const void* g, u32 sz) {
    asm volatile("cp.async.cg.shared.global [%0], [%1], 16, %2;"
                 :: "r"(s), "l"((u64)__cvta_generic_to_global((void*)g)), "r"(sz));
}
#define CP_COMMIT() asm volatile("cp.async.commit_group;")
#define CP_WAIT1()  asm volatile("cp.async.wait_group 1;")
#define SWZ(o) ((o) ^ (((o) >> 3) & 0x70))
#define LDSM4(r0, r1, r2, r3, addr) \
    asm volatile("ldmatrix.sync.aligned.m8n8.x4.shared.b16 {%0,%1,%2,%3}, [%4];" \
        : "=r"(r0), "=r"(r1), "=r"(r2), "=r"(r3) : "r"(addr))
#define MMA16816(d, a0, a1, a2, a3, b0, b1) \
    asm volatile("mma.sync.aligned.m16n8k16.row.col.f32.f16.f16.f32 " \
        "{%0,%1,%2,%3}, {%4,%5,%6,%7}, {%8,%9}, {%0,%1,%2,%3};" \
        : "+f"((d)[0]), "+f"((d)[1]), "+f"((d)[2]), "+f"((d)[3]) \
        : "r"(a0), "r"(a1), "r"(a2), "r"(a3), "r"(b0), "r"(b1))

// ---------------- weight / BN prep -------------------------------------------
__global__ void bconv_k(const float* __restrict__ w) {
    size_t i = (size_t)blockIdx.x * 256 + threadIdx.x;
    if (i >= (size_t)C_ * C_ * 9) return;
    int k = (int)(i % 9);
    size_t t = i / 9;
    int c = (int)(t % C_), o = (int)(t / C_);
    g_B1[(size_t)o * LDB1 + k * C_ + c] =
        __half_as_ushort(__float2half_rn(w[i]));
}

__global__ void bfin_k(W10 ws) {
    size_t i = (size_t)blockIdx.x * 256 + threadIdx.x;
    if (i >= (size_t)5 * 512 * 1536) return;
    int cc = (int)(i % 1536);
    size_t t = i / 1536;
    int j = (int)(t % 512), b = (int)(t / 512);
    int half = cc / 768, c = cc % 768;
    const int CH[5] = {30, 100, 150, 220, 268};
    float v = 0.f;
    if (j < CH[b]) {
        if (half == 0) v = ws.a[b][j * C_ + c];
        else if (b >= 2) v = ws.b[b][j * C_ + c];
    }
    g_Bfin[((size_t)b * 512 + j) * LDBF + cc] =
        __half_as_ushort(__float2half_rn(v));
}

__global__ void bnprep_k(const float* g, const float* bt, const float* mu,
                         const float* var, const float* cb) {
    int c = blockIdx.x * 256 + threadIdx.x;
    if (c >= C_) return;
    float inv = g[c] / sqrtf(var[c] + 1e-5f);
    g_scale[c] = inv;
    g_shift[c] = cb[c] * inv + bt[c] - mu[c] * inv;
}

// Weff[o][n] = sum_cout hw[o][cout] * g_B1[cout][n]    (coalesced fp16 source)
// grid 108 (n-chunks of 64), block 256 = 64 cols x 4 cout-groups of 192
__global__ void weff_k(const float* __restrict__ ow, const float* __restrict__ mw) {
    extern __shared__ float shw[];               // [768][28] = c*28+o
    int tid = threadIdx.x;
    int n0 = blockIdx.x * 64;
    for (int i = tid; i < 27 * C_; i += 256) {
        int o = i / C_, c = i % C_;
        shw[c * 28 + o] = (o < 18) ? ow[o * C_ + c] : mw[(o - 18) * C_ + c];
    }
    __syncthreads();
    int col = tid & 63, grp = tid >> 6;
    float acc[28];
#pragma unroll
    for (int o = 0; o < 28; o++) acc[o] = 0.f;
    const u16* b1 = g_B1 + n0 + col;
    for (int c = grp * 192; c < grp * 192 + 192; c++) {
        float bv = __half2float(__ushort_as_half(b1[(size_t)c * LDB1]));
        const float4* h4 = (const float4*)&shw[c * 28];
#pragma unroll
        for (int j = 0; j < 7; j++) {
            float4 h = h4[j];
            acc[4 * j]     += bv * h.x;
            acc[4 * j + 1] += bv * h.y;
            acc[4 * j + 2] += bv * h.z;
            acc[4 * j + 3] += bv * h.w;
        }
    }
    __syncthreads();
    float* red = shw;                            // reuse: [256][27]
#pragma unroll
    for (int o = 0; o < 27; o++) red[tid * 27 + o] = acc[o];
    __syncthreads();
    if (grp == 0) {
#pragma unroll
        for (int o = 0; o < 27; o++) {
            float s = red[col * 27 + o] + red[(64 + col) * 27 + o] +
                      red[(128 + col) * 27 + o] + red[(192 + col) * 27 + o];
            g_Weff[(size_t)o * LDB1 + n0 + col] =
                __half_as_ushort(__float2half_rn(s));
        }
    }
}

__global__ void beprep_k(const float* __restrict__ ow, const float* __restrict__ mw,
                         const float* __restrict__ cb) {
    int tid = threadIdx.x;                       // 256
    int o = tid >> 3, l8 = tid & 7;
    float s = 0.f;
    if (o < 27) {
        const float* wr = (o < 18) ? (ow + o * 768) : (mw + (o - 18) * 768);
        for (int c = l8; c < 768; c += 8) s += wr[c] * cb[c];
    }
#pragma unroll
    for (int d = 4; d; d >>= 1) s += __shfl_xor_sync(0xffffffffu, s, d);
    if (l8 == 0) g_be[o] = (o < 27) ? s : 0.f;
}

// ---------------- hi-only writer ---------------------------------------------
__device__ __forceinline__ void store_hi4(u32* base32, int tid, float4 v) {
    base32[2 * tid]     = packh2(v.x, v.y);
    base32[2 * tid + 1] = packh2(v.z, v.w);
}

__global__ void xsplit_k(X5 xs) {
    int row = blockIdx.x, b = blockIdx.y;
    float4 v = ((const float4*)(xs.p[b] + (size_t)row * C_))[threadIdx.x];
    u32* base32 = (u32*)(g_X2 + ((size_t)b * 4096 + row) * LDX);
    store_hi4(base32, threadIdx.x, v);
}

// ---------------- narrow head GEMM: g_omx = im2col(g_X2) @ Weff^T + be -------
__global__ void __launch_bounds__(256, 1) gemm_off() {
    extern __shared__ char sm[];
    u32 sbase = s2u(sm);
    const int tid = threadIdx.x;
    const int wid = tid >> 5, lane = tid & 31;
    const int m0 = blockIdx.x * TM;

    auto loadStage = [&](int s, int kc) {
        u32 sb = sbase + s * STG_OFF;
        u32 bbs = sb + 16384;
        int seg = kc / 12, c0 = (kc % 12) << 6;
        {
            int row = tid >> 3, c16 = tid & 7;
            u32 off = (u32)(row * 128 + c16 * 16);
            cpa16(bbs + SWZ(off),
                  g_Weff + (size_t)row * LDB1 + seg * 768 + c0 + c16 * 8);
        }
        int ky = seg / 3 - 1, kx = seg % 3 - 1;
#pragma unroll
        for (int it = 0; it < 4; it++) {
            int i = it * 256 + tid;
            int row = i >> 3, c16 = i & 7;
            int grow = m0 + row;
            int p = grow & 1023;
            int hh = (p >> 5) + ky, ww = (p & 31) + kx;
            bool ok = hh >= 0 && hh < 32 && ww >= 0 && ww < 32;
            int srow = ok ? (grow - p + (hh << 5) + ww) : 0;
            u32 off = (u32)(row * 128 + c16 * 16);
            cpa16z(sb + SWZ(off), g_X2 + (size_t)srow * LDX + c0 + c16 * 8,
                   ok ? 16u : 0u);
        }
        CP_COMMIT();
    };

    float acc[4][4];
#pragma unroll
    for (int i = 0; i < 4; i++)
#pragma unroll
        for (int q = 0; q < 4; q++) acc[i][q] = 0.f;

    loadStage(0, 0);
    loadStage(1, 1);

    for (int kc = 0; kc < 108; kc++) {
        CP_WAIT1();
        __syncthreads();
        u32 ab = sbase + (kc % 3) * STG_OFF;
        u32 bb = ab + 16384;
#pragma unroll
        for (int ks = 0; ks < 4; ks++) {
            u32 afr[4];
            int arw = wid * 16 + (lane & 15);
            u32 aoff = (u32)(arw * 128 + ks * 32 + (lane >> 4) * 16);
            LDSM4(afr[0], afr[1], afr[2], afr[3], ab + SWZ(aoff));
#pragma unroll
            for (int np2 = 0; np2 < 2; np2++) {
                int g = lane >> 3;
                int brow = np2 * 16 + ((g >> 1) & 1) * 8 + (lane & 7);
                u32 boff = (u32)(brow * 128 + ks * 32 + (g & 1) * 16);
                u32 bfr[4];
                LDSM4(bfr[0], bfr[1], bfr[2], bfr[3], bb + SWZ(boff));
                MMA16816(acc[2 * np2], afr[0], afr[1], afr[2], afr[3],
                         bfr[0], bfr[1]);
                MMA16816(acc[2 * np2 + 1], afr[0], afr[1], afr[2], afr[3],
                         bfr[2], bfr[3]);
            }
        }
        __syncthreads();
        int kl = kc + 2;
        if (kl < 108) loadStage(kl % 3, kl);
        else CP_COMMIT();
    }

    int quad = lane >> 2, qt = lane & 3;
#pragma unroll
    for (int np = 0; np < 4; np++) {
        int colb = np * 8 + 2 * qt;
#pragma unroll
        for (int hh = 0; hh < 2; hh++) {
            int row = m0 + wid * 16 + quad + hh * 8;
            g_omx[(size_t)row * 32 + colb]     = acc[np][2 * hh]     + g_be[colb];
            g_omx[(size_t)row * 32 + colb + 1] = acc[np][2 * hh + 1] + g_be[colb + 1];
        }
    }
}

// ---------------- per-row offsets + softmax ----------------------------------
__global__ void offlite_k() {
    int row = blockIdx.x * 256 + threadIdx.x;   // 0..20479
    int z = row >> 10, p = row & 1023;
    const float* src = g_omx + (size_t)row * 32;
    float res[27];
#pragma unroll
    for (int o = 0; o < 27; o++) res[o] = src[o];
#pragma unroll
    for (int o = 0; o < 18; o++) g_off[z * 18 * P_ + o * P_ + p] = res[o];
    float mx = res[18];
#pragma unroll
    for (int k = 1; k < 9; k++) mx = fmaxf(mx, res[18 + k]);
    float e[9], sum = 0.f;
#pragma unroll
    for (int k = 0; k < 9; k++) { e[k] = expf(res[18 + k] - mx); sum += e[k]; }
    float r = 1.f / sum;
#pragma unroll
    for (int k = 0; k < 9; k++) g_mask[z * 9 * P_ + p * 9 + k] = e[k] * r;
}

// ---------------- deformable sampling from fp16 g_X2 -------------------------
__device__ __forceinline__ void addtap(float4& a, const uint2* xb, int pix,
                                       int t, float w) {
    uint2 s = xb[(size_t)pix * 192 + t];
    __half2 h0 = *(__half2*)&s.x, h1 = *(__half2*)&s.y;
    float2 f0 = __half22float2(h0), f1 = __half22float2(h1);
    a.x += w * f0.x; a.y += w * f0.y; a.z += w * f1.x; a.w += w * f1.y;
}

__global__ void sample_split_k() {
    int p = blockIdx.x, k = blockIdx.y, z = blockIdx.z;
    float dy = g_off[z * 18 * P_ + (2 * k) * P_ + p];
    float dx = g_off[z * 18 * P_ + (2 * k + 1) * P_ + p];
    float m = g_mask[z * 9 * P_ + k * P_ + p];            // raw-reshape quirk
    int h = p >> 5, w = p & 31;
    float py = (float)(h - 1 + k / 3) + dy;
    float px = (float)(w - 1 + k % 3) + dx;
    float y0f = floorf(py), x0f = floorf(px);
    float wy = py - y0f, wx = px - x0f;
    int y0 = (int)y0f, x0 = (int)x0f;
    float w00 = (1.f - wy) * (1.f - wx), w01 = (1.f - wy) * wx;
    float w10 = wy * (1.f - wx),         w11 = wy * wx;
    bool vy0 = (y0 >= 0) && (y0 < 32),  vy1 = (y0 >= -1) && (y0 < 31);
    bool vx0 = (x0 >= 0) && (x0 < 32),  vx1 = (x0 >= -1) && (x0 < 31);
    const uint2* xb = (const uint2*)(g_X2 + (size_t)z * P_ * LDX);
    int t = threadIdx.x;
    float4 a = make_float4(0.f, 0.f, 0.f, 0.f);
    if (vy0 && vx0) addtap(a, xb, y0 * 32 + x0, t, w00);
    if (vy0 && vx1) addtap(a, xb, y0 * 32 + x0 + 1, t, w01);
    if (vy1 && vx0) addtap(a, xb, (y0 + 1) * 32 + x0, t, w10);
    if (vy1 && vx1) addtap(a, xb, (y0 + 1) * 32 + x0 + 1, t, w11);
    a.x *= m; a.y *= m; a.z *= m; a.w *= m;
    size_t row = (size_t)z * P_ + p;
    u32* base32 = (u32*)(g_A1 + row * LDA1 + (size_t)k * C_);
    store_hi4(base32, t, a);
}

// ---------------- mma.sync fp16 GEMM -----------------------------------------
// kc: seg = kc/12, c0 = (kc%12)*64
// AK=3: GEMM2, A = g_A1 (seg=tap), NK=108          -> MODE 1
// AK=2: final, A = seg?g_X2:g_blk, NK=12/24        -> MODE 2
template<int AK, int MODE>
__global__ void __launch_bounds__(THREADS, 1) gemm_mma(
    const u16* __restrict__ Bg, long ldb, int NKin, X5 xs,
    const float* __restrict__ aux, float* __restrict__ outp, Fin fin)
{
    extern __shared__ char sm[];
    u32 sbase = s2u(sm);
    const int tid = threadIdx.x;
    const int wid = tid >> 5, lane = tid & 31;
    const int wm = wid >> 2, wn = wid & 3;
    const int m0 = blockIdx.y * TM, n0 = blockIdx.x * TN;

    int NK = NKin, chN = 0, coff = 0, bsel = 0;
    const u16* Bb0 = Bg;
    if (MODE == 2) {
        bsel = blockIdx.z;
        chN = fin.chN[bsel]; coff = fin.coff[bsel]; NK = fin.nk[bsel];
        Bb0 = Bg + (size_t)bsel * 512 * ldb;
        if (n0 >= chN) return;
    }
    const char* Bbase = (const char*)(Bb0 + (size_t)n0 * ldb);
    const long ldbb = ldb * 2;
    const int arow = tid >> 2, aq = tid & 3;      // 128 rows x 4 thr, 32B each
    int grow = m0 + (MODE == 2 ? bsel * 4096 : 0) + arow;

    auto loadStage = [&](int s, int kc) {
        u32 sb = sbase + s * STG_BYTES;
        u32 bb = sb + 16384;
        int seg = kc / 12, c0 = (kc % 12) << 6;
        const char* Bgp = Bbase + (size_t)(seg * C_ + c0) * 2;
#pragma unroll
        for (int it = 0; it < 4; it++) {
            int i = it * THREADS + tid;
            int row = i >> 3, c16 = i & 7;
            u32 off = (u32)(row * 128 + c16 * 16);
            cpa16(bb + SWZ(off), Bgp + (size_t)row * ldbb + c16 * 16);
        }
        u32 off = (u32)(arow * 128 + aq * 32);
        u32 d0 = sb + SWZ(off), d1 = sb + SWZ(off + 16);
        int elem = c0 + aq * 16;
        if (AK == 3) {
            const u16* src = g_A1 + (size_t)grow * LDA1 + seg * C_ + elem;
            cpa16(d0, src);
            cpa16(d1, src + 8);
        } else {
            const u16* base = seg ? g_X2 : g_blk;
            const u16* src = base + (size_t)grow * LDX + elem;
            cpa16(d0, src);
            cpa16(d1, src + 8);
        }
        CP_COMMIT();
    };

    float acc[2][8][4];
#pragma unroll
    for (int i = 0; i < 2; i++)
#pragma unroll
        for (int j = 0; j < 8; j++)
#pragma unroll
            for (int q = 0; q < 4; q++) acc[i][j][q] = 0.f;

    loadStage(0, 0);
    loadStage(1, 1);

    for (int kc = 0; kc < NK; kc++) {
        CP_WAIT1();
        __syncthreads();
        u32 ab = sbase + (kc % 3) * STG_BYTES;
        u32 bb = ab + 16384;
#pragma unroll
        for (int ks = 0; ks < 4; ks++) {
            u32 afr[2][4];
#pragma unroll
            for (int ms = 0; ms < 2; ms++) {
                int row = wm * 32 + ms * 16 + (lane & 15);
                u32 off = (u32)(row * 128 + ks * 32 + (lane >> 4) * 16);
                LDSM4(afr[ms][0], afr[ms][1], afr[ms][2], afr[ms][3], ab + SWZ(off));
            }
#pragma unroll
            for (int np = 0; np < 4; np++) {
                int g = lane >> 3;
                int row = wn * 64 + np * 16 + ((g >> 1) & 1) * 8 + (lane & 7);
                u32 off = (u32)(row * 128 + ks * 32 + (g & 1) * 16);
                u32 bfr[4];
                LDSM4(bfr[0], bfr[1], bfr[2], bfr[3], bb + SWZ(off));
#pragma unroll
                for (int ms = 0; ms < 2; ms++) {
                    MMA16816(acc[ms][2 * np], afr[ms][0], afr[ms][1], afr[ms][2],
                             afr[ms][3], bfr[0], bfr[1]);
                    MMA16816(acc[ms][2 * np + 1], afr[ms][0], afr[ms][1], afr[ms][2],
                             afr[ms][3], bfr[2], bfr[3]);
                }
            }
        }
        __syncthreads();
        int kl = kc + 2;
        if (kl < NK) loadStage(kl % 3, kl);
        else CP_COMMIT();
    }

    // epilogue
    int quad = lane >> 2, qt = lane & 3;
#pragma unroll
    for (int ms = 0; ms < 2; ms++) {
#pragma unroll
        for (int ns = 0; ns < 8; ns++) {
            int colb = n0 + wn * 64 + ns * 8 + 2 * qt;
#pragma unroll
            for (int hh = 0; hh < 2; hh++) {
                int row = m0 + wm * 32 + ms * 16 + quad + hh * 8;
                float v0 = acc[ms][ns][2 * hh], v1 = acc[ms][ns][2 * hh + 1];
                if (MODE == 1) {
                    float t0 = fmaxf(v0 * g_scale[colb] + g_shift[colb], 0.f);
                    float t1 = fmaxf(v1 * g_scale[colb + 1] + g_shift[colb + 1], 0.f);
                    ((u32*)(g_blk + (size_t)row * LDX))[colb >> 1] = packh2(t0, t1);
                } else {
                    // concat is along channels: plain 4096 spatial rows
                    if (colb < chN)
                        outp[(size_t)row * C_ + coff + colb] =
                            v0 + aux[(size_t)row * C_ + coff + colb];
                    if (colb + 1 < chN)
                        outp[(size_t)row * C_ + coff + colb + 1] =
                            v1 + aux[(size_t)row * C_ + coff + colb + 1];
                }
            }
        }
    }
}

// ---------------- launch -----------------------------------------------------
extern "C" void kernel_launch(void* const* d_in, const int* in_sizes, int n_in,
                              void* d_out, int out_size) {
    static u16 *pB1 = 0, *pBf = 0;
    if (!pB1) {
        cudaGetSymbolAddress((void**)&pB1, g_B1);
        cudaGetSymbolAddress((void**)&pBf, g_Bfin);
        cudaFuncSetAttribute(gemm_mma<3, 1>,
                             cudaFuncAttributeMaxDynamicSharedMemorySize, DYN_SMEM);
        cudaFuncSetAttribute(gemm_mma<2, 2>,
                             cudaFuncAttributeMaxDynamicSharedMemorySize, DYN_SMEM);
        cudaFuncSetAttribute(gemm_off,
                             cudaFuncAttributeMaxDynamicSharedMemorySize, DYN_OFF);
        cudaFuncSetAttribute(weff_k,
                             cudaFuncAttributeMaxDynamicSharedMemorySize, DYN_WEFF);
    }
    X5 xs;
    for (int i = 0; i < 5; i++) xs.p[i] = (const float*)d_in[i];
    const float* conv_w = (const float*)d_in[5];
    const float* conv_b = (const float*)d_in[6];
    const float* offw   = (const float*)d_in[7];
    const float* maskw  = (const float*)d_in[8];
    W10 ws;
    const int waIdx[5] = {0, 1, 2, 4, 6};
    for (int b = 0; b < 5; b++) {
        ws.a[b] = (const float*)d_in[13 + waIdx[b]];
        ws.b[b] = (b >= 2) ? (const float*)d_in[13 + waIdx[b] + 1] : ws.a[b];
    }
    float* out = (float*)d_out;
    Fin fin;
    const int CH[5]   = {30, 100, 150, 220, 268};
    const int COFF[5] = {0, 30, 130, 280, 500};
    for (int b = 0; b < 5; b++) {
        fin.chN[b] = CH[b]; fin.coff[b] = COFF[b]; fin.nk[b] = (b < 2) ? 12 : 24;
    }

    bconv_k<<<(int)(((size_t)C_ * C_ * 9 + 255) / 256), 256>>>(conv_w);
    bfin_k<<<(int)(((size_t)5 * 512 * 1536 + 255) / 256), 256>>>(ws);
    bnprep_k<<<3, 256>>>((const float*)d_in[9], (const float*)d_in[10],
                         (const float*)d_in[11], (const float*)d_in[12], conv_b);
    weff_k<<<108, 256, DYN_WEFF>>>(offw, maskw);
    beprep_k<<<1, 256>>>(offw, maskw, conv_b);
    xsplit_k<<<dim3(4096, 5), 192>>>(xs);

    gemm_off<<<160, 256, DYN_OFF>>>();
    offlite_k<<<80, 256>>>();
    sample_split_k<<<dim3(P_, 9, 20), 192>>>();
    gemm_mma<3, 1><<<dim3(3, 160), THREADS, DYN_SMEM>>>(
        pB1, LDB1, 108, xs, nullptr, nullptr, fin);
    gemm_mma<2, 2><<<dim3(2, 32, 5), THREADS, DYN_SMEM>>>(
        pBf, LDBF, 0, xs, xs.p[4], out, fin);
}